// round 10
// baseline (speedup 1.0000x reference)
#include <cuda_runtime.h>
#include <cuda_bf16.h>
#include <cstdint>
#include <cstddef>

#define NROWS 8192
#define FIN   512
#define FOUT  512

// ---------------- scratch (device globals; no allocations allowed) ----------------
__device__ __align__(1024) __nv_bfloat16 g_adjT[67108864ull];   // adj^T bf16 [i][j], 128MB
__device__ __align__(1024) __nv_bfloat16 g_xh[NROWS * FIN];     // X hi limb  [j][c]
__device__ __align__(1024) __nv_bfloat16 g_xl[NROWS * FIN];     // X lo limb
__device__ __align__(1024) __nv_bfloat16 g_wth[FIN * FOUT];     // W^T hi [f][c]
__device__ __align__(1024) __nv_bfloat16 g_wtl[FIN * FOUT];     // W^T lo
__device__ __align__(1024) __nv_bfloat16 g_xwth[NROWS * FOUT];  // (XW)^T hi [f][j]
__device__ __align__(1024) __nv_bfloat16 g_xwtl[NROWS * FOUT];  // (XW)^T lo
__device__ int   g_deg[NROWS];
__device__ float g_norm[NROWS];

// ---------------- helpers ----------------
__device__ __forceinline__ uint32_t smem_u32(const void* p) {
    uint32_t a;
    asm("{ .reg .u64 t; cvta.to.shared.u64 t, %1; cvt.u32.u64 %0, t; }" : "=r"(a) : "l"(p));
    return a;
}

__device__ __forceinline__ void cp16(uint32_t sdst, const void* gsrc) {
    asm volatile("cp.async.cg.shared.global [%0], [%1], 16;" :: "r"(sdst), "l"(gsrc));
}
__device__ __forceinline__ void cp_commit() { asm volatile("cp.async.commit_group;" ::: "memory"); }
template <int N>
__device__ __forceinline__ void cp_wait() { asm volatile("cp.async.wait_group %0;" :: "n"(N) : "memory"); }

__device__ __forceinline__ void ldsm4(uint32_t* r, uint32_t addr) {
    asm volatile("ldmatrix.sync.aligned.m8n8.x4.shared.b16 {%0,%1,%2,%3}, [%4];"
                 : "=r"(r[0]), "=r"(r[1]), "=r"(r[2]), "=r"(r[3]) : "r"(addr));
}

__device__ __forceinline__ void mma16816(float* c, const uint32_t* a, uint32_t b0, uint32_t b1) {
    asm volatile("mma.sync.aligned.m16n8k16.row.col.f32.bf16.bf16.f32 "
                 "{%0,%1,%2,%3}, {%4,%5,%6,%7}, {%8,%9}, {%0,%1,%2,%3};"
                 : "+f"(c[0]), "+f"(c[1]), "+f"(c[2]), "+f"(c[3])
                 : "r"(a[0]), "r"(a[1]), "r"(a[2]), "r"(a[3]), "r"(b0), "r"(b1));
}

__device__ __forceinline__ uint32_t pack_bf2(float x, float y) {
    __nv_bfloat16 hx = __float2bfloat16_rn(x), hy = __float2bfloat16_rn(y);
    uint16_t ux, uy;
    ux = *reinterpret_cast<uint16_t*>(&hx);
    uy = *reinterpret_cast<uint16_t*>(&hy);
    return (uint32_t)ux | ((uint32_t)uy << 16);
}

// Load [ROWS x 64] bf16 K-major tile (rows of 128B), SW128 swizzle, 256 threads.
template <int ROWS>
__device__ __forceinline__ void ldtile(uint32_t sdst, const __nv_bfloat16* g,
                                       int row0, int k0, int ldk, int tid) {
    constexpr int CH = ROWS * 8 / 256;
#pragma unroll
    for (int p = 0; p < CH; ++p) {
        int idx = p * 256 + tid;
        int r = idx >> 3, ck = idx & 7;
        const char* src = (const char*)(g + (size_t)(row0 + r) * ldk + k0) + ck * 16;
        cp16(sdst + r * 128 + ((uint32_t)(ck ^ (r & 7)) << 4), src);
    }
}

// ---------------- prep kernels ----------------
__global__ void zero_deg_kernel() {
    int i = blockIdx.x * blockDim.x + threadIdx.x;
    if (i < NROWS) g_deg[i] = 0;
}

__global__ void norm_kernel() {
    int i = blockIdx.x * blockDim.x + threadIdx.x;
    if (i < NROWS) g_norm[i] = rsqrtf(fmaxf((float)g_deg[i], 1.0f));
}

__global__ void splitx_kernel(const float* __restrict__ X) {
    int stride = gridDim.x * blockDim.x;
    for (int idx = blockIdx.x * blockDim.x + threadIdx.x; idx < NROWS * FIN; idx += stride) {
        float v = X[idx];
        __nv_bfloat16 h = __float2bfloat16_rn(v);
        g_xh[idx] = h;
        g_xl[idx] = __float2bfloat16_rn(v - __bfloat162float(h));
    }
}

__global__ void prepw_kernel(const float* __restrict__ W) {
    int idx = blockIdx.x * blockDim.x + threadIdx.x;   // idx = c*FOUT + f (coalesced read)
    if (idx < FIN * FOUT) {
        int c = idx / FOUT, f = idx % FOUT;
        float v = W[idx];
        __nv_bfloat16 h = __float2bfloat16_rn(v);
        g_wth[f * FIN + c] = h;
        g_wtl[f * FIN + c] = __float2bfloat16_rn(v - __bfloat162float(h));
    }
}

// Transpose adj (int32 [j][i]) -> adjT (bf16 [i][j]), fused in-degree.
__global__ void transpose_adj_kernel(const int* __restrict__ adj) {
    __shared__ __nv_bfloat16 tile[128][129];
    __shared__ int degs[128];
    int i0 = blockIdx.x * 128, j0 = blockIdx.y * 128;
    int t = threadIdx.x;            // 0..255
    int il = t & 127, half = t >> 7;
    if (t < 128) degs[t] = 0;
    __syncthreads();
    int local = 0;
#pragma unroll 8
    for (int rr = 0; rr < 128; rr += 2) {
        int jl = rr + half;
        int v = adj[(size_t)(j0 + jl) * NROWS + i0 + il];
        local += v;
        tile[il][jl] = __float2bfloat16_rn((float)v);
    }
    atomicAdd(&degs[il], local);
    __syncthreads();
    if (t < 128) atomicAdd(&g_deg[i0 + t], degs[t]);
#pragma unroll 8
    for (int rr = 0; rr < 128; rr += 2) {
        int il2 = rr + half;
        g_adjT[(size_t)(i0 + il2) * NROWS + j0 + il] = tile[il2][il];
    }
}

// =====================================================================================
// GEMM1': D[f][j] = sum_c Wt[f][c] * X[j][c], 3 limb products (hh + hl + lh).
// M=512(f) x N=8192(j) x K=512(c). Tile 128x256x64, 2 stages, 256 threads (2m x 4n warps).
// Epilogue: split D into bf16 hi/lo limbs -> g_xwth/g_xwtl (row-major [f][j]).
// =====================================================================================
#define G1_SAH   0
#define G1_SAL   16384
#define G1_SBH   32768
#define G1_SBL   65536
#define G1_STAGE 98304
#define G1_SMEM  (2 * G1_STAGE)
#define G1_NIT   (FIN / 64)

__global__ void __launch_bounds__(256, 1) gemm1_kernel() {
    extern __shared__ __align__(1024) char smem[];
    uint32_t sb = smem_u32(smem);
    int tid = threadIdx.x, lane = tid & 31, warp = tid >> 5;
    int wm = warp >> 2, wn = warp & 3;         // 2 x 4 warp grid
    int n0 = blockIdx.x * 256;                 // j
    int m0 = blockIdx.y * 128;                 // f

    int lr = lane & 15, lc = lane >> 4;
    int sw = lr & 7;
    uint32_t aRow[4], bRow[4], chk[4];
#pragma unroll
    for (int mi = 0; mi < 4; ++mi) aRow[mi] = (wm * 64 + mi * 16 + lr) * 128;
#pragma unroll
    for (int ng = 0; ng < 4; ++ng) bRow[ng] = (wn * 64 + ng * 16 + lr) * 128;
#pragma unroll
    for (int kc = 0; kc < 4; ++kc) chk[kc] = (uint32_t)((2 * kc + lc) ^ sw) << 4;

    float c[4][8][4];
#pragma unroll
    for (int mi = 0; mi < 4; ++mi)
#pragma unroll
        for (int ni = 0; ni < 8; ++ni)
#pragma unroll
            for (int q = 0; q < 4; ++q) c[mi][ni][q] = 0.0f;

#pragma unroll
    for (int s = 0; s < 2; ++s) {
        uint32_t st = sb + s * G1_STAGE;
        int k0 = s * 64;
        ldtile<128>(st + G1_SAH, g_wth, m0, k0, FIN, tid);
        ldtile<128>(st + G1_SAL, g_wtl, m0, k0, FIN, tid);
        ldtile<256>(st + G1_SBH, g_xh, n0, k0, FIN, tid);
        ldtile<256>(st + G1_SBL, g_xl, n0, k0, FIN, tid);
        cp_commit();
    }

    for (int it = 0; it < G1_NIT; ++it) {
        int s = it & 1;
        uint32_t st = sb + s * G1_STAGE;
        cp_wait<1>();
        __syncthreads();
#pragma unroll
        for (int kc = 0; kc < 4; ++kc) {
            uint32_t ah[4][4], al[4][4];
#pragma unroll
            for (int mi = 0; mi < 4; ++mi) {
                ldsm4(ah[mi], st + G1_SAH + aRow[mi] + chk[kc]);
                ldsm4(al[mi], st + G1_SAL + aRow[mi] + chk[kc]);
            }
#pragma unroll
            for (int ng = 0; ng < 4; ++ng) {
                uint32_t bh[4], bl[4];
                ldsm4(bh, st + G1_SBH + bRow[ng] + chk[kc]);
                ldsm4(bl, st + G1_SBL + bRow[ng] + chk[kc]);
#pragma unroll
                for (int mi = 0; mi < 4; ++mi) {
                    mma16816(c[mi][ng * 2 + 0], ah[mi], bh[0], bh[2]);
                    mma16816(c[mi][ng * 2 + 1], ah[mi], bh[1], bh[3]);
                    mma16816(c[mi][ng * 2 + 0], ah[mi], bl[0], bl[2]);
                    mma16816(c[mi][ng * 2 + 1], ah[mi], bl[1], bl[3]);
                    mma16816(c[mi][ng * 2 + 0], al[mi], bh[0], bh[2]);
                    mma16816(c[mi][ng * 2 + 1], al[mi], bh[1], bh[3]);
                }
            }
        }
        __syncthreads();
        if (it + 2 < G1_NIT) {
            int k0 = (it + 2) * 64;
            ldtile<128>(st + G1_SAH, g_wth, m0, k0, FIN, tid);
            ldtile<128>(st + G1_SAL, g_wtl, m0, k0, FIN, tid);
            ldtile<256>(st + G1_SBH, g_xh, n0, k0, FIN, tid);
            ldtile<256>(st + G1_SBL, g_xl, n0, k0, FIN, tid);
        }
        cp_commit();
    }

    // Epilogue: write hi/lo bf16 limbs of (XW)^T [f][j]
    int fr = m0 + wm * 64 + (lane >> 2);
    int jc = n0 + wn * 64 + (lane & 3) * 2;
#pragma unroll
    for (int mi = 0; mi < 4; ++mi) {
        int fa = fr + mi * 16, fb = fa + 8;
#pragma unroll
        for (int ni = 0; ni < 8; ++ni) {
            int j = jc + ni * 8;
            {
                float v0 = c[mi][ni][0], v1 = c[mi][ni][1];
                __nv_bfloat16 h0 = __float2bfloat16_rn(v0), h1 = __float2bfloat16_rn(v1);
                float l0 = v0 - __bfloat162float(h0), l1 = v1 - __bfloat162float(h1);
                size_t off = (size_t)fa * NROWS + j;
                *reinterpret_cast<uint32_t*>(g_xwth + off) = pack_bf2(__bfloat162float(h0), __bfloat162float(h1));
                *reinterpret_cast<uint32_t*>(g_xwtl + off) = pack_bf2(l0, l1);
            }
            {
                float v0 = c[mi][ni][2], v1 = c[mi][ni][3];
                __nv_bfloat16 h0 = __float2bfloat16_rn(v0), h1 = __float2bfloat16_rn(v1);
                float l0 = v0 - __bfloat162float(h0), l1 = v1 - __bfloat162float(h1);
                size_t off = (size_t)fb * NROWS + j;
                *reinterpret_cast<uint32_t*>(g_xwth + off) = pack_bf2(__bfloat162float(h0), __bfloat162float(h1));
                *reinterpret_cast<uint32_t*>(g_xwtl + off) = pack_bf2(l0, l1);
            }
        }
    }
}

// =====================================================================================
// GEMM2: D[i][f] = sum_j adjT[i][j] * (xwt_hi + xwt_lo)[f][j]; fused norm + relu.
// M=8192(i) x N=512(f) x K=8192(j). Tile 128x256x64, 2 stages, 256 threads.
// Grid 2(n) x 64(m) = 128 CTAs = one wave.
// =====================================================================================
#define G2_SA    0
#define G2_SBH   16384
#define G2_SBL   49152
#define G2_STAGE 81920
#define G2_SMEM  (2 * G2_STAGE)
#define G2_NIT   (NROWS / 64)

__global__ void __launch_bounds__(256, 1) gemm2_kernel(float* __restrict__ out) {
    extern __shared__ __align__(1024) char smem[];
    uint32_t sb = smem_u32(smem);
    int tid = threadIdx.x, lane = tid & 31, warp = tid >> 5;
    int wm = warp >> 2, wn = warp & 3;
    int n0 = blockIdx.x * 256;                 // f
    int m0 = blockIdx.y * 128;                 // i

    int lr = lane & 15, lc = lane >> 4;
    int sw = lr & 7;
    uint32_t aRow[4], bRow[4], chk[4];
#pragma unroll
    for (int mi = 0; mi < 4; ++mi) aRow[mi] = (wm * 64 + mi * 16 + lr) * 128;
#pragma unroll
    for (int ng = 0; ng < 4; ++ng) bRow[ng] = (wn * 64 + ng * 16 + lr) * 128;
#pragma unroll
    for (int kc = 0; kc < 4; ++kc) chk[kc] = (uint32_t)((2 * kc + lc) ^ sw) << 4;

    float c[4][8][4];
#pragma unroll
    for (int mi = 0; mi < 4; ++mi)
#pragma unroll
        for (int ni = 0; ni < 8; ++ni)
#pragma unroll
            for (int q = 0; q < 4; ++q) c[mi][ni][q] = 0.0f;

#pragma unroll
    for (int s = 0; s < 2; ++s) {
        uint32_t st = sb + s * G2_STAGE;
        int k0 = s * 64;
        ldtile<128>(st + G2_SA, g_adjT, m0, k0, NROWS, tid);
        ldtile<256>(st + G2_SBH, g_xwth, n0, k0, NROWS, tid);
        ldtile<256>(st + G2_SBL, g_xwtl, n0, k0, NROWS, tid);
        cp_commit();
    }

    for (int it = 0; it < G2_NIT; ++it) {
        int s = it & 1;
        uint32_t st = sb + s * G2_STAGE;
        cp_wait<1>();
        __syncthreads();
#pragma unroll
        for (int kc = 0; kc < 4; ++kc) {
            uint32_t a[4][4];
#pragma unroll
            for (int mi = 0; mi < 4; ++mi)
                ldsm4(a[mi], st + G2_SA + aRow[mi] + chk[kc]);
#pragma unroll
            for (int ng = 0; ng < 4; ++ng) {
                uint32_t bh[4], bl[4];
                ldsm4(bh, st + G2_SBH + bRow[ng] + chk[kc]);
                ldsm4(bl, st + G2_SBL + bRow[ng] + chk[kc]);
#pragma unroll
                for (int mi = 0; mi < 4; ++mi) {
                    mma16816(c[mi][ng * 2 + 0], a[mi], bh[0], bh[2]);
                    mma16816(c[mi][ng * 2 + 1], a[mi], bh[1], bh[3]);
                    mma16816(c[mi][ng * 2 + 0], a[mi], bl[0], bl[2]);
                    mma16816(c[mi][ng * 2 + 1], a[mi], bl[1], bl[3]);
                }
            }
        }
        __syncthreads();
        if (it + 2 < G2_NIT) {
            int k0 = (it + 2) * 64;
            ldtile<128>(st + G2_SA, g_adjT, m0, k0, NROWS, tid);
            ldtile<256>(st + G2_SBH, g_xwth, n0, k0, NROWS, tid);
            ldtile<256>(st + G2_SBL, g_xwtl, n0, k0, NROWS, tid);
        }
        cp_commit();
    }

    // Epilogue: out[i][f] = relu(c * norm[i])
    int ir = m0 + wm * 64 + (lane >> 2);
    int fc = n0 + wn * 64 + (lane & 3) * 2;
#pragma unroll
    for (int mi = 0; mi < 4; ++mi) {
        int ia = ir + mi * 16, ib = ia + 8;
        float na = g_norm[ia], nb = g_norm[ib];
        float* oa = out + (size_t)ia * FOUT;
        float* ob = out + (size_t)ib * FOUT;
#pragma unroll
        for (int ni = 0; ni < 8; ++ni) {
            int f = fc + ni * 8;
            float2 va, vb;
            va.x = fmaxf(c[mi][ni][0] * na, 0.0f);
            va.y = fmaxf(c[mi][ni][1] * na, 0.0f);
            vb.x = fmaxf(c[mi][ni][2] * nb, 0.0f);
            vb.y = fmaxf(c[mi][ni][3] * nb, 0.0f);
            *reinterpret_cast<float2*>(oa + f) = va;
            *reinterpret_cast<float2*>(ob + f) = vb;
        }
    }
}

// ---------------- launch ----------------
extern "C" void kernel_launch(void* const* d_in, const int* in_sizes, int n_in,
                              void* d_out, int out_size) {
    const float* X   = (const float*)d_in[0];
    const int*   adj = (const int*)d_in[1];
    const float* W   = (const float*)d_in[2];
    float*       out = (float*)d_out;

    cudaFuncSetAttribute(gemm1_kernel, cudaFuncAttributeMaxDynamicSharedMemorySize, G1_SMEM);
    cudaFuncSetAttribute(gemm2_kernel, cudaFuncAttributeMaxDynamicSharedMemorySize, G2_SMEM);

    zero_deg_kernel<<<(NROWS + 255) / 256, 256>>>();
    splitx_kernel<<<1024, 256>>>(X);
    prepw_kernel<<<(FIN * FOUT + 255) / 256, 256>>>(W);
    transpose_adj_kernel<<<dim3(64, 64), 256>>>(adj);
    norm_kernel<<<(NROWS + 255) / 256, 256>>>();

    gemm1_kernel<<<dim3(NROWS / 256, FIN / 128), 256, G1_SMEM>>>();
    gemm2_kernel<<<dim3(FOUT / 256, NROWS / 128), 256, G2_SMEM>>>(out);
}

// round 11
// speedup vs baseline: 1.5532x; 1.5532x over previous
#include <cuda_runtime.h>
#include <cuda_fp16.h>
#include <cstdint>
#include <cstddef>

#define NROWS 8192
#define FIN   512
#define FOUT  512

// ---------------- scratch (device globals; no allocations allowed) ----------------
__device__ __align__(1024) __half g_adjT[67108864ull];   // adj^T fp16 [i][j], 128MB
__device__ __align__(1024) __half g_xh[NROWS * FIN];     // X hi limb  [j][c]
__device__ __align__(1024) __half g_xl[NROWS * FIN];     // X lo limb
__device__ __align__(1024) __half g_wth[FIN * FOUT];     // W^T hi [f][c]
__device__ __align__(1024) __half g_wtl[FIN * FOUT];     // W^T lo
__device__ __align__(1024) __half g_xwt[NROWS * FOUT];   // (XW)^T fp16 [f][j]
__device__ int   g_deg[NROWS];
__device__ float g_norm[NROWS];

// ---------------- helpers ----------------
__device__ __forceinline__ uint32_t smem_u32(const void* p) {
    uint32_t a;
    asm("{ .reg .u64 t; cvta.to.shared.u64 t, %1; cvt.u32.u64 %0, t; }" : "=r"(a) : "l"(p));
    return a;
}

__device__ __forceinline__ void cp16(uint32_t sdst, const void* gsrc) {
    asm volatile("cp.async.cg.shared.global [%0], [%1], 16;" :: "r"(sdst), "l"(gsrc));
}
__device__ __forceinline__ void cp_commit() { asm volatile("cp.async.commit_group;" ::: "memory"); }
template <int N>
__device__ __forceinline__ void cp_wait() { asm volatile("cp.async.wait_group %0;" :: "n"(N) : "memory"); }

__device__ __forceinline__ void ldsm4(uint32_t* r, uint32_t addr) {
    asm volatile("ldmatrix.sync.aligned.m8n8.x4.shared.b16 {%0,%1,%2,%3}, [%4];"
                 : "=r"(r[0]), "=r"(r[1]), "=r"(r[2]), "=r"(r[3]) : "r"(addr));
}

__device__ __forceinline__ void mma16816(float* c, const uint32_t* a, uint32_t b0, uint32_t b1) {
    asm volatile("mma.sync.aligned.m16n8k16.row.col.f32.f16.f16.f32 "
                 "{%0,%1,%2,%3}, {%4,%5,%6,%7}, {%8,%9}, {%0,%1,%2,%3};"
                 : "+f"(c[0]), "+f"(c[1]), "+f"(c[2]), "+f"(c[3])
                 : "r"(a[0]), "r"(a[1]), "r"(a[2]), "r"(a[3]), "r"(b0), "r"(b1));
}

__device__ __forceinline__ uint32_t pack_h2(float x, float y) {
    __half hx = __float2half_rn(x), hy = __float2half_rn(y);
    uint16_t ux = *reinterpret_cast<uint16_t*>(&hx);
    uint16_t uy = *reinterpret_cast<uint16_t*>(&hy);
    return (uint32_t)ux | ((uint32_t)uy << 16);
}

// Load [ROWS x 64] fp16 K-major tile (rows of 128B), SW128 swizzle, 256 threads.
template <int ROWS>
__device__ __forceinline__ void ldtile(uint32_t sdst, const __half* g,
                                       int row0, int k0, int ldk, int tid) {
    constexpr int CH = ROWS * 8 / 256;
#pragma unroll
    for (int p = 0; p < CH; ++p) {
        int idx = p * 256 + tid;
        int r = idx >> 3, ck = idx & 7;
        const char* src = (const char*)(g + (size_t)(row0 + r) * ldk + k0) + ck * 16;
        cp16(sdst + r * 128 + ((uint32_t)(ck ^ (r & 7)) << 4), src);
    }
}

// ---------------- prep kernels ----------------
__global__ void zero_deg_kernel() {
    int i = blockIdx.x * blockDim.x + threadIdx.x;
    if (i < NROWS) g_deg[i] = 0;
}

__global__ void norm_kernel() {
    int i = blockIdx.x * blockDim.x + threadIdx.x;
    if (i < NROWS) g_norm[i] = rsqrtf(fmaxf((float)g_deg[i], 1.0f));
}

__global__ void splitx_kernel(const float* __restrict__ X) {
    int stride = gridDim.x * blockDim.x;
    for (int idx = blockIdx.x * blockDim.x + threadIdx.x; idx < NROWS * FIN; idx += stride) {
        float v = X[idx];
        __half h = __float2half_rn(v);
        g_xh[idx] = h;
        g_xl[idx] = __float2half_rn(v - __half2float(h));
    }
}

__global__ void prepw_kernel(const float* __restrict__ W) {
    int idx = blockIdx.x * blockDim.x + threadIdx.x;   // idx = c*FOUT + f (coalesced read)
    if (idx < FIN * FOUT) {
        int c = idx / FOUT, f = idx % FOUT;
        float v = W[idx];
        __half h = __float2half_rn(v);
        g_wth[f * FIN + c] = h;
        g_wtl[f * FIN + c] = __float2half_rn(v - __half2float(h));
    }
}

// Transpose adj (int32 [j][i]) -> adjT (fp16 [i][j]), fused in-degree.
// 128x128 tile, 256 threads; vectorized 8B stores on the write side.
__global__ void transpose_adj_kernel(const int* __restrict__ adj) {
    __shared__ __half tile[128][132];
    __shared__ int degs[128];
    int i0 = blockIdx.x * 128, j0 = blockIdx.y * 128;
    int t = threadIdx.x;            // 0..255
    int il = t & 127, hf = t >> 7;
    if (t < 128) degs[t] = 0;
    __syncthreads();
    int local = 0;
#pragma unroll 8
    for (int rr = 0; rr < 128; rr += 2) {
        int jl = rr + hf;
        int v = adj[(size_t)(j0 + jl) * NROWS + i0 + il];
        local += v;
        tile[il][jl] = __int2half_rn(v);
    }
    atomicAdd(&degs[il], local);
    __syncthreads();
    if (t < 128) atomicAdd(&g_deg[i0 + t], degs[t]);
    int ilw = t >> 5;               // 0..7
    int jl4 = (t & 31) * 4;
#pragma unroll
    for (int pp = 0; pp < 16; ++pp) {
        int r = pp * 8 + ilw;
        uint2 v;
        v.x = *reinterpret_cast<const uint32_t*>(&tile[r][jl4]);
        v.y = *reinterpret_cast<const uint32_t*>(&tile[r][jl4 + 2]);
        *reinterpret_cast<uint2*>(&g_adjT[(size_t)(i0 + r) * NROWS + j0 + jl4]) = v;
    }
}

// =====================================================================================
// GEMM1': D[f][j] = sum_c Wt[f][c] * X[j][c], 3 fp16 limb products (hh + hl + lh).
// M=512(f) x N=8192(j) x K=512(c). Tile 128x256x64, 2 stages, 256 threads (2m x 4n).
// Epilogue: round D to a SINGLE fp16 -> g_xwt (row-major [f][j]).
// =====================================================================================
#define G1_SAH   0
#define G1_SAL   16384
#define G1_SBH   32768
#define G1_SBL   65536
#define G1_STAGE 98304
#define G1_SMEM  (2 * G1_STAGE)
#define G1_NIT   (FIN / 64)

__global__ void __launch_bounds__(256, 1) gemm1_kernel() {
    extern __shared__ __align__(1024) char smem[];
    uint32_t sb = smem_u32(smem);
    int tid = threadIdx.x, lane = tid & 31, warp = tid >> 5;
    int wm = warp >> 2, wn = warp & 3;
    int n0 = blockIdx.x * 256;                 // j
    int m0 = blockIdx.y * 128;                 // f

    int lr = lane & 15, lc = lane >> 4;
    int sw = lr & 7;
    uint32_t aRow[4], bRow[4], chk[4];
#pragma unroll
    for (int mi = 0; mi < 4; ++mi) aRow[mi] = (wm * 64 + mi * 16 + lr) * 128;
#pragma unroll
    for (int ng = 0; ng < 4; ++ng) bRow[ng] = (wn * 64 + ng * 16 + lr) * 128;
#pragma unroll
    for (int kc = 0; kc < 4; ++kc) chk[kc] = (uint32_t)((2 * kc + lc) ^ sw) << 4;

    float c[4][8][4];
#pragma unroll
    for (int mi = 0; mi < 4; ++mi)
#pragma unroll
        for (int ni = 0; ni < 8; ++ni)
#pragma unroll
            for (int q = 0; q < 4; ++q) c[mi][ni][q] = 0.0f;

#pragma unroll
    for (int s = 0; s < 2; ++s) {
        uint32_t st = sb + s * G1_STAGE;
        int k0 = s * 64;
        ldtile<128>(st + G1_SAH, g_wth, m0, k0, FIN, tid);
        ldtile<128>(st + G1_SAL, g_wtl, m0, k0, FIN, tid);
        ldtile<256>(st + G1_SBH, g_xh, n0, k0, FIN, tid);
        ldtile<256>(st + G1_SBL, g_xl, n0, k0, FIN, tid);
        cp_commit();
    }

    for (int it = 0; it < G1_NIT; ++it) {
        int s = it & 1;
        uint32_t st = sb + s * G1_STAGE;
        cp_wait<1>();
        __syncthreads();
#pragma unroll
        for (int kc = 0; kc < 4; ++kc) {
            uint32_t ah[4][4], al[4][4];
#pragma unroll
            for (int mi = 0; mi < 4; ++mi) {
                ldsm4(ah[mi], st + G1_SAH + aRow[mi] + chk[kc]);
                ldsm4(al[mi], st + G1_SAL + aRow[mi] + chk[kc]);
            }
#pragma unroll
            for (int ng = 0; ng < 4; ++ng) {
                uint32_t bh[4], bl[4];
                ldsm4(bh, st + G1_SBH + bRow[ng] + chk[kc]);
                ldsm4(bl, st + G1_SBL + bRow[ng] + chk[kc]);
#pragma unroll
                for (int mi = 0; mi < 4; ++mi) {
                    mma16816(c[mi][ng * 2 + 0], ah[mi], bh[0], bh[2]);
                    mma16816(c[mi][ng * 2 + 1], ah[mi], bh[1], bh[3]);
                    mma16816(c[mi][ng * 2 + 0], ah[mi], bl[0], bl[2]);
                    mma16816(c[mi][ng * 2 + 1], ah[mi], bl[1], bl[3]);
                    mma16816(c[mi][ng * 2 + 0], al[mi], bh[0], bh[2]);
                    mma16816(c[mi][ng * 2 + 1], al[mi], bh[1], bh[3]);
                }
            }
        }
        __syncthreads();
        if (it + 2 < G1_NIT) {
            int k0 = (it + 2) * 64;
            ldtile<128>(st + G1_SAH, g_wth, m0, k0, FIN, tid);
            ldtile<128>(st + G1_SAL, g_wtl, m0, k0, FIN, tid);
            ldtile<256>(st + G1_SBH, g_xh, n0, k0, FIN, tid);
            ldtile<256>(st + G1_SBL, g_xl, n0, k0, FIN, tid);
        }
        cp_commit();
    }

    // Epilogue: write single fp16 (XW)^T [f][j]
    int fr = m0 + wm * 64 + (lane >> 2);
    int jc = n0 + wn * 64 + (lane & 3) * 2;
#pragma unroll
    for (int mi = 0; mi < 4; ++mi) {
        int fa = fr + mi * 16, fb = fa + 8;
#pragma unroll
        for (int ni = 0; ni < 8; ++ni) {
            int j = jc + ni * 8;
            *reinterpret_cast<uint32_t*>(g_xwt + (size_t)fa * NROWS + j) =
                pack_h2(c[mi][ni][0], c[mi][ni][1]);
            *reinterpret_cast<uint32_t*>(g_xwt + (size_t)fb * NROWS + j) =
                pack_h2(c[mi][ni][2], c[mi][ni][3]);
        }
    }
}

// =====================================================================================
// GEMM2: D[i][f] = sum_j adjT[i][j] * xwt[f][j]; fused norm + relu.
// M=8192(i) x N=512(f) x K=8192(j). Tile 128x256x64, 3 stages, 256 threads.
// Grid 2(n) x 64(m) = 128 CTAs = one wave. Single fp16 B operand.
// =====================================================================================
#define G2_SA    0
#define G2_SB    16384
#define G2_STAGE 49152
#define G2_SMEM  (3 * G2_STAGE)
#define G2_NIT   (NROWS / 64)

__global__ void __launch_bounds__(256, 1) gemm2_kernel(float* __restrict__ out) {
    extern __shared__ __align__(1024) char smem[];
    uint32_t sb = smem_u32(smem);
    int tid = threadIdx.x, lane = tid & 31, warp = tid >> 5;
    int wm = warp >> 2, wn = warp & 3;
    int n0 = blockIdx.x * 256;                 // f
    int m0 = blockIdx.y * 128;                 // i

    int lr = lane & 15, lc = lane >> 4;
    int sw = lr & 7;
    uint32_t aRow[4], bRow[4], chk[4];
#pragma unroll
    for (int mi = 0; mi < 4; ++mi) aRow[mi] = (wm * 64 + mi * 16 + lr) * 128;
#pragma unroll
    for (int ng = 0; ng < 4; ++ng) bRow[ng] = (wn * 64 + ng * 16 + lr) * 128;
#pragma unroll
    for (int kc = 0; kc < 4; ++kc) chk[kc] = (uint32_t)((2 * kc + lc) ^ sw) << 4;

    float c[4][8][4];
#pragma unroll
    for (int mi = 0; mi < 4; ++mi)
#pragma unroll
        for (int ni = 0; ni < 8; ++ni)
#pragma unroll
            for (int q = 0; q < 4; ++q) c[mi][ni][q] = 0.0f;

#pragma unroll
    for (int s = 0; s < 3; ++s) {
        uint32_t st = sb + s * G2_STAGE;
        int k0 = s * 64;
        ldtile<128>(st + G2_SA, g_adjT, m0, k0, NROWS, tid);
        ldtile<256>(st + G2_SB, g_xwt, n0, k0, NROWS, tid);
        cp_commit();
    }

    for (int it = 0; it < G2_NIT; ++it) {
        int s = it % 3;
        uint32_t st = sb + s * G2_STAGE;
        cp_wait<2>();
        __syncthreads();
#pragma unroll
        for (int kc = 0; kc < 4; ++kc) {
            uint32_t a[4][4];
#pragma unroll
            for (int mi = 0; mi < 4; ++mi)
                ldsm4(a[mi], st + G2_SA + aRow[mi] + chk[kc]);
#pragma unroll
            for (int ng = 0; ng < 4; ++ng) {
                uint32_t b[4];
                ldsm4(b, st + G2_SB + bRow[ng] + chk[kc]);
#pragma unroll
                for (int mi = 0; mi < 4; ++mi) {
                    mma16816(c[mi][ng * 2 + 0], a[mi], b[0], b[2]);
                    mma16816(c[mi][ng * 2 + 1], a[mi], b[1], b[3]);
                }
            }
        }
        __syncthreads();
        if (it + 3 < G2_NIT) {
            int k0 = (it + 3) * 64;
            ldtile<128>(st + G2_SA, g_adjT, m0, k0, NROWS, tid);
            ldtile<256>(st + G2_SB, g_xwt, n0, k0, NROWS, tid);
        }
        cp_commit();
    }

    // Epilogue: out[i][f] = relu(c * norm[i])
    int ir = m0 + wm * 64 + (lane >> 2);
    int fc = n0 + wn * 64 + (lane & 3) * 2;
#pragma unroll
    for (int mi = 0; mi < 4; ++mi) {
        int ia = ir + mi * 16, ib = ia + 8;
        float na = g_norm[ia], nb = g_norm[ib];
        float* oa = out + (size_t)ia * FOUT;
        float* ob = out + (size_t)ib * FOUT;
#pragma unroll
        for (int ni = 0; ni < 8; ++ni) {
            int f = fc + ni * 8;
            float2 va, vb;
            va.x = fmaxf(c[mi][ni][0] * na, 0.0f);
            va.y = fmaxf(c[mi][ni][1] * na, 0.0f);
            vb.x = fmaxf(c[mi][ni][2] * nb, 0.0f);
            vb.y = fmaxf(c[mi][ni][3] * nb, 0.0f);
            *reinterpret_cast<float2*>(oa + f) = va;
            *reinterpret_cast<float2*>(ob + f) = vb;
        }
    }
}

// ---------------- launch ----------------
extern "C" void kernel_launch(void* const* d_in, const int* in_sizes, int n_in,
                              void* d_out, int out_size) {
    const float* X   = (const float*)d_in[0];
    const int*   adj = (const int*)d_in[1];
    const float* W   = (const float*)d_in[2];
    float*       out = (float*)d_out;

    cudaFuncSetAttribute(gemm1_kernel, cudaFuncAttributeMaxDynamicSharedMemorySize, G1_SMEM);
    cudaFuncSetAttribute(gemm2_kernel, cudaFuncAttributeMaxDynamicSharedMemorySize, G2_SMEM);

    zero_deg_kernel<<<(NROWS + 255) / 256, 256>>>();
    splitx_kernel<<<1024, 256>>>(X);
    prepw_kernel<<<(FIN * FOUT + 255) / 256, 256>>>(W);
    transpose_adj_kernel<<<dim3(64, 64), 256>>>(adj);
    norm_kernel<<<(NROWS + 255) / 256, 256>>>();

    gemm1_kernel<<<dim3(NROWS / 256, FIN / 128), 256, G1_SMEM>>>();
    gemm2_kernel<<<dim3(FOUT / 256, NROWS / 128), 256, G2_SMEM>>>(out);
}

// round 12
// speedup vs baseline: 1.6934x; 1.0902x over previous
#include <cuda_runtime.h>
#include <cuda_fp16.h>
#include <cstdint>
#include <cstddef>

#define NROWS 8192
#define FIN   512
#define FOUT  512

// ---------------- scratch (device globals; no allocations allowed) ----------------
__device__ __align__(1024) __half g_xh[NROWS * FIN];     // X hi limb  [j][c]
__device__ __align__(1024) __half g_xl[NROWS * FIN];     // X lo limb
__device__ __align__(1024) __half g_wth[FIN * FOUT];     // W^T hi [f][c]
__device__ __align__(1024) __half g_wtl[FIN * FOUT];     // W^T lo
__device__ __align__(1024) __half g_xwt[NROWS * FOUT];   // (XW)^T fp16 [f][j]

// ---------------- helpers ----------------
__device__ __forceinline__ uint32_t smem_u32(const void* p) {
    uint32_t a;
    asm("{ .reg .u64 t; cvta.to.shared.u64 t, %1; cvt.u32.u64 %0, t; }" : "=r"(a) : "l"(p));
    return a;
}

__device__ __forceinline__ void cp16(uint32_t sdst, const void* gsrc) {
    asm volatile("cp.async.cg.shared.global [%0], [%1], 16;" :: "r"(sdst), "l"(gsrc));
}
__device__ __forceinline__ void cp_commit() { asm volatile("cp.async.commit_group;" ::: "memory"); }
template <int N>
__device__ __forceinline__ void cp_wait() { asm volatile("cp.async.wait_group %0;" :: "n"(N) : "memory"); }

__device__ __forceinline__ void ldsm4(uint32_t* r, uint32_t addr) {
    asm volatile("ldmatrix.sync.aligned.m8n8.x4.shared.b16 {%0,%1,%2,%3}, [%4];"
                 : "=r"(r[0]), "=r"(r[1]), "=r"(r[2]), "=r"(r[3]) : "r"(addr));
}
__device__ __forceinline__ void ldsm4t(uint32_t* r, uint32_t addr) {
    asm volatile("ldmatrix.sync.aligned.m8n8.x4.trans.shared.b16 {%0,%1,%2,%3}, [%4];"
                 : "=r"(r[0]), "=r"(r[1]), "=r"(r[2]), "=r"(r[3]) : "r"(addr));
}

__device__ __forceinline__ void mma16816(float* c, const uint32_t* a, uint32_t b0, uint32_t b1) {
    asm volatile("mma.sync.aligned.m16n8k16.row.col.f32.f16.f16.f32 "
                 "{%0,%1,%2,%3}, {%4,%5,%6,%7}, {%8,%9}, {%0,%1,%2,%3};"
                 : "+f"(c[0]), "+f"(c[1]), "+f"(c[2]), "+f"(c[3])
                 : "r"(a[0]), "r"(a[1]), "r"(a[2]), "r"(a[3]), "r"(b0), "r"(b1));
}

__device__ __forceinline__ uint32_t pack_h2(float x, float y) {
    __half hx = __float2half_rn(x), hy = __float2half_rn(y);
    uint16_t ux = *reinterpret_cast<uint16_t*>(&hx);
    uint16_t uy = *reinterpret_cast<uint16_t*>(&hy);
    return (uint32_t)ux | ((uint32_t)uy << 16);
}

// Load [ROWS x 64] fp16 K-major tile (rows of 128B), SW128 swizzle, 256 threads.
template <int ROWS>
__device__ __forceinline__ void ldtile(uint32_t sdst, const __half* g,
                                       int row0, int k0, int ldk, int tid) {
    constexpr int CH = ROWS * 8 / 256;
#pragma unroll
    for (int p = 0; p < CH; ++p) {
        int idx = p * 256 + tid;
        int r = idx >> 3, ck = idx & 7;
        const char* src = (const char*)(g + (size_t)(row0 + r) * ldk + k0) + ck * 16;
        cp16(sdst + r * 128 + ((uint32_t)(ck ^ (r & 7)) << 4), src);
    }
}

// ---------------- prep kernels ----------------
__global__ void splitx_kernel(const float* __restrict__ X) {
    int stride = gridDim.x * blockDim.x;
    for (int idx = blockIdx.x * blockDim.x + threadIdx.x; idx < NROWS * FIN; idx += stride) {
        float v = X[idx];
        __half h = __float2half_rn(v);
        g_xh[idx] = h;
        g_xl[idx] = __float2half_rn(v - __half2float(h));
    }
}

__global__ void prepw_kernel(const float* __restrict__ W) {
    int idx = blockIdx.x * blockDim.x + threadIdx.x;   // idx = c*FOUT + f (coalesced read)
    if (idx < FIN * FOUT) {
        int c = idx / FOUT, f = idx % FOUT;
        float v = W[idx];
        __half h = __float2half_rn(v);
        g_wth[f * FIN + c] = h;
        g_wtl[f * FIN + c] = __float2half_rn(v - __half2float(h));
    }
}

// =====================================================================================
// GEMM1': D[f][j] = sum_c Wt[f][c] * X[j][c], 3 fp16 limb products (hh + hl + lh).
// M=512(f) x N=8192(j) x K=512(c). Tile 128x256x64, 2 stages, 256 threads (2m x 4n).
// Epilogue: round D to a SINGLE fp16 -> g_xwt (row-major [f][j]).
// =====================================================================================
#define G1_SAH   0
#define G1_SAL   16384
#define G1_SBH   32768
#define G1_SBL   65536
#define G1_STAGE 98304
#define G1_SMEM  (2 * G1_STAGE)
#define G1_NIT   (FIN / 64)

__global__ void __launch_bounds__(256, 1) gemm1_kernel() {
    extern __shared__ __align__(1024) char smem[];
    uint32_t sb = smem_u32(smem);
    int tid = threadIdx.x, lane = tid & 31, warp = tid >> 5;
    int wm = warp >> 2, wn = warp & 3;
    int n0 = blockIdx.x * 256;                 // j
    int m0 = blockIdx.y * 128;                 // f

    int lr = lane & 15, lc = lane >> 4;
    int sw = lr & 7;
    uint32_t aRow[4], bRow[4], chk[4];
#pragma unroll
    for (int mi = 0; mi < 4; ++mi) aRow[mi] = (wm * 64 + mi * 16 + lr) * 128;
#pragma unroll
    for (int ng = 0; ng < 4; ++ng) bRow[ng] = (wn * 64 + ng * 16 + lr) * 128;
#pragma unroll
    for (int kc = 0; kc < 4; ++kc) chk[kc] = (uint32_t)((2 * kc + lc) ^ sw) << 4;

    float c[4][8][4];
#pragma unroll
    for (int mi = 0; mi < 4; ++mi)
#pragma unroll
        for (int ni = 0; ni < 8; ++ni)
#pragma unroll
            for (int q = 0; q < 4; ++q) c[mi][ni][q] = 0.0f;

#pragma unroll
    for (int s = 0; s < 2; ++s) {
        uint32_t st = sb + s * G1_STAGE;
        int k0 = s * 64;
        ldtile<128>(st + G1_SAH, g_wth, m0, k0, FIN, tid);
        ldtile<128>(st + G1_SAL, g_wtl, m0, k0, FIN, tid);
        ldtile<256>(st + G1_SBH, g_xh, n0, k0, FIN, tid);
        ldtile<256>(st + G1_SBL, g_xl, n0, k0, FIN, tid);
        cp_commit();
    }

    for (int it = 0; it < G1_NIT; ++it) {
        int s = it & 1;
        uint32_t st = sb + s * G1_STAGE;
        cp_wait<1>();
        __syncthreads();
#pragma unroll
        for (int kc = 0; kc < 4; ++kc) {
            uint32_t ah[4][4], al[4][4];
#pragma unroll
            for (int mi = 0; mi < 4; ++mi) {
                ldsm4(ah[mi], st + G1_SAH + aRow[mi] + chk[kc]);
                ldsm4(al[mi], st + G1_SAL + aRow[mi] + chk[kc]);
            }
#pragma unroll
            for (int ng = 0; ng < 4; ++ng) {
                uint32_t bh[4], bl[4];
                ldsm4(bh, st + G1_SBH + bRow[ng] + chk[kc]);
                ldsm4(bl, st + G1_SBL + bRow[ng] + chk[kc]);
#pragma unroll
                for (int mi = 0; mi < 4; ++mi) {
                    mma16816(c[mi][ng * 2 + 0], ah[mi], bh[0], bh[2]);
                    mma16816(c[mi][ng * 2 + 1], ah[mi], bh[1], bh[3]);
                    mma16816(c[mi][ng * 2 + 0], ah[mi], bl[0], bl[2]);
                    mma16816(c[mi][ng * 2 + 1], ah[mi], bl[1], bl[3]);
                    mma16816(c[mi][ng * 2 + 0], al[mi], bh[0], bh[2]);
                    mma16816(c[mi][ng * 2 + 1], al[mi], bh[1], bh[3]);
                }
            }
        }
        __syncthreads();
        if (it + 2 < G1_NIT) {
            int k0 = (it + 2) * 64;
            ldtile<128>(st + G1_SAH, g_wth, m0, k0, FIN, tid);
            ldtile<128>(st + G1_SAL, g_wtl, m0, k0, FIN, tid);
            ldtile<256>(st + G1_SBH, g_xh, n0, k0, FIN, tid);
            ldtile<256>(st + G1_SBL, g_xl, n0, k0, FIN, tid);
        }
        cp_commit();
    }

    // Epilogue: write single fp16 (XW)^T [f][j]
    int fr = m0 + wm * 64 + (lane >> 2);
    int jc = n0 + wn * 64 + (lane & 3) * 2;
#pragma unroll
    for (int mi = 0; mi < 4; ++mi) {
        int fa = fr + mi * 16, fb = fa + 8;
#pragma unroll
        for (int ni = 0; ni < 8; ++ni) {
            int j = jc + ni * 8;
            *reinterpret_cast<uint32_t*>(g_xwt + (size_t)fa * NROWS + j) =
                pack_h2(c[mi][ni][0], c[mi][ni][1]);
            *reinterpret_cast<uint32_t*>(g_xwt + (size_t)fb * NROWS + j) =
                pack_h2(c[mi][ni][2], c[mi][ni][3]);
        }
    }
}

// =====================================================================================
// GEMM2: D[i][f] = sum_j adj[j][i] * xwt[f][j]; fused in-degree + norm + relu.
// A operand loaded DIRECTLY from int32 adj (no transpose pass): cp.async int tile
// [64j x 128i], in-kernel {0,1}->fp16 convert into [j][i] smem, ldmatrix.trans.
// Degree accumulated during conversion (register sums -> smem reduce -> rsqrt).
// M=8192(i) x N=512(f) x K=8192(j). Tile 128x256x64, 3 stages, 256 threads.
// Grid 2(n) x 64(m) = 128 CTAs = one wave.
// =====================================================================================
#define G2_SAI   0            // int32 A stages: 3 x 32768
#define G2_SB    98304        // fp16 B stages:  3 x 32768
#define G2_SAH   196608       // fp16 converted A: 16384 (single buffer)
#define G2_SMEM  212992
#define G2_NIT   (NROWS / 64)

__global__ void __launch_bounds__(256, 1) gemm2_kernel(const int* __restrict__ adj,
                                                       float* __restrict__ out) {
    __shared__ int sdeg[128];
    extern __shared__ __align__(1024) char smem[];
    uint32_t sb = smem_u32(smem);
    int tid = threadIdx.x, lane = tid & 31, warp = tid >> 5;
    int wm = warp >> 2, wn = warp & 3;
    int n0 = blockIdx.x * 256;                 // f
    int m0 = blockIdx.y * 128;                 // i

    if (tid < 128) sdeg[tid] = 0;

    // B (xwt) ldmatrix addresses (non-trans), rows = f, 128B rows
    int lr = lane & 15, lc = lane >> 4;
    int sw = lr & 7;
    uint32_t bRow[4], chk[4];
#pragma unroll
    for (int ng = 0; ng < 4; ++ng) bRow[ng] = (wn * 64 + ng * 16 + lr) * 128;
#pragma unroll
    for (int kc = 0; kc < 4; ++kc) chk[kc] = (uint32_t)((2 * kc + lc) ^ sw) << 4;

    // A trans-ldmatrix addresses: smem tile S[j][i], 256B rows, chunk swizzle ci^(j&7).
    // fragment (mi, kc): logical A rows i0=wm*64+mi*16, cols j0=kc*16.
    int jb   = ((lane >> 4) & 1) * 8 + (lane & 7);   // row within 16-j window
    int icof = ((lane >> 3) & 1) * 8;                // +8 i for groups 1 and 3
    uint32_t aAddr[4];
#pragma unroll
    for (int mi = 0; mi < 4; ++mi) {
        int ic = wm * 64 + mi * 16 + icof;
        int ci = ic >> 3;
        aAddr[mi] = (uint32_t)(jb * 256 + ((ci ^ (lane & 7)) << 4));
    }

    // conversion assignment: thread -> 4 i-columns x 8 j-rows per tile
    int cv_i4 = (tid & 31) * 4;
    int cv_jb = (tid >> 5) * 8;
    int cv_ci = cv_i4 >> 3;
    int d0 = 0, d1 = 0, d2 = 0, d3 = 0;

    float c[4][8][4];
#pragma unroll
    for (int mi = 0; mi < 4; ++mi)
#pragma unroll
        for (int ni = 0; ni < 8; ++ni)
#pragma unroll
            for (int q = 0; q < 4; ++q) c[mi][ni][q] = 0.0f;

    // prefetch 3 stages: int A tile [64 x 128] int32 (512B rows) + fp16 B tile
#pragma unroll
    for (int s = 0; s < 3; ++s) {
        int k0 = s * 64;
#pragma unroll
        for (int p = 0; p < 8; ++p) {
            int idx = p * 256 + tid;
            int r = idx >> 5, ck = idx & 31;
            cp16(sb + G2_SAI + s * 32768 + r * 512 + ck * 16,
                 adj + (size_t)(k0 + r) * NROWS + m0 + ck * 4);
        }
        ldtile<256>(sb + G2_SB + s * 32768, g_xwt, n0, k0, NROWS, tid);
        cp_commit();
    }

    for (int it = 0; it < G2_NIT; ++it) {
        int s = it % 3;
        cp_wait<2>();
        __syncthreads();

        // ---- convert int32 {0,1} tile -> fp16 [j][i] tile; accumulate degree ----
        {
            const char* srcb = smem + G2_SAI + s * 32768 + cv_i4 * 4;
            char* dstb = smem + G2_SAH + (cv_i4 & 7) * 2;
#pragma unroll
            for (int jj = 0; jj < 8; ++jj) {
                int j = cv_jb + jj;
                int4 v = *reinterpret_cast<const int4*>(srcb + j * 512);
                uint32_t p01 = (uint32_t)(v.x | (v.y << 16)) * 0x3C00u;
                uint32_t p23 = (uint32_t)(v.z | (v.w << 16)) * 0x3C00u;
                d0 += v.x; d1 += v.y; d2 += v.z; d3 += v.w;
                uint2 pv; pv.x = p01; pv.y = p23;
                *reinterpret_cast<uint2*>(dstb + j * 256 + ((cv_ci ^ (j & 7)) << 4)) = pv;
            }
        }
        __syncthreads();

        // ---- compute ----
        uint32_t stb = sb + G2_SB + s * 32768;
#pragma unroll
        for (int kc = 0; kc < 4; ++kc) {
            uint32_t a[4][4];
#pragma unroll
            for (int mi = 0; mi < 4; ++mi)
                ldsm4t(a[mi], sb + G2_SAH + kc * 4096 + aAddr[mi]);
#pragma unroll
            for (int ng = 0; ng < 4; ++ng) {
                uint32_t b[4];
                ldsm4(b, stb + bRow[ng] + chk[kc]);
#pragma unroll
                for (int mi = 0; mi < 4; ++mi) {
                    mma16816(c[mi][ng * 2 + 0], a[mi], b[0], b[2]);
                    mma16816(c[mi][ng * 2 + 1], a[mi], b[1], b[3]);
                }
            }
        }
        __syncthreads();

        // ---- prefetch it+3 into just-freed stage ----
        if (it + 3 < G2_NIT) {
            int k0 = (it + 3) * 64;
#pragma unroll
            for (int p = 0; p < 8; ++p) {
                int idx = p * 256 + tid;
                int r = idx >> 5, ck = idx & 31;
                cp16(sb + G2_SAI + s * 32768 + r * 512 + ck * 16,
                     adj + (size_t)(k0 + r) * NROWS + m0 + ck * 4);
            }
            ldtile<256>(sb + G2_SB + s * 32768, g_xwt, n0, k0, NROWS, tid);
        }
        cp_commit();
    }

    // ---- degree reduce -> norm ----
    atomicAdd(&sdeg[cv_i4 + 0], d0);
    atomicAdd(&sdeg[cv_i4 + 1], d1);
    atomicAdd(&sdeg[cv_i4 + 2], d2);
    atomicAdd(&sdeg[cv_i4 + 3], d3);
    __syncthreads();

    // ---- epilogue: out[i][f] = relu(c * rsqrt(max(deg,1))) ----
    int il = wm * 64 + (lane >> 2);
    int fc = n0 + wn * 64 + (lane & 3) * 2;
#pragma unroll
    for (int mi = 0; mi < 4; ++mi) {
        int ial = il + mi * 16, ibl = ial + 8;
        float na = rsqrtf(fmaxf((float)sdeg[ial], 1.0f));
        float nb = rsqrtf(fmaxf((float)sdeg[ibl], 1.0f));
        float* oa = out + (size_t)(m0 + ial) * FOUT;
        float* ob = out + (size_t)(m0 + ibl) * FOUT;
#pragma unroll
        for (int ni = 0; ni < 8; ++ni) {
            int f = fc + ni * 8;
            float2 va, vb;
            va.x = fmaxf(c[mi][ni][0] * na, 0.0f);
            va.y = fmaxf(c[mi][ni][1] * na, 0.0f);
            vb.x = fmaxf(c[mi][ni][2] * nb, 0.0f);
            vb.y = fmaxf(c[mi][ni][3] * nb, 0.0f);
            *reinterpret_cast<float2*>(oa + f) = va;
            *reinterpret_cast<float2*>(ob + f) = vb;
        }
    }
}

// ---------------- launch ----------------
extern "C" void kernel_launch(void* const* d_in, const int* in_sizes, int n_in,
                              void* d_out, int out_size) {
    const float* X   = (const float*)d_in[0];
    const int*   adj = (const int*)d_in[1];
    const float* W   = (const float*)d_in[2];
    float*       out = (float*)d_out;

    cudaFuncSetAttribute(gemm1_kernel, cudaFuncAttributeMaxDynamicSharedMemorySize, G1_SMEM);
    cudaFuncSetAttribute(gemm2_kernel, cudaFuncAttributeMaxDynamicSharedMemorySize, G2_SMEM);

    splitx_kernel<<<1024, 256>>>(X);
    prepw_kernel<<<(FIN * FOUT + 255) / 256, 256>>>(W);

    gemm1_kernel<<<dim3(NROWS / 256, FIN / 128), 256, G1_SMEM>>>();
    gemm2_kernel<<<dim3(FOUT / 256, NROWS / 128), 256, G2_SMEM>>>(adj, out);
}

// round 13
// speedup vs baseline: 1.7593x; 1.0390x over previous
#include <cuda_runtime.h>
#include <cuda_fp16.h>
#include <cstdint>
#include <cstddef>

#define NROWS 8192
#define FIN   512
#define FOUT  512

// ---------------- scratch (device globals; no allocations allowed) ----------------
__device__ __align__(1024) __half g_xh[NROWS * FIN];     // X hi limb  [j][c]
__device__ __align__(1024) __half g_xl[NROWS * FIN];     // X lo limb
__device__ __align__(1024) __half g_wth[FIN * FOUT];     // W^T hi [f][c]
__device__ __align__(1024) __half g_wtl[FIN * FOUT];     // W^T lo
__device__ __align__(1024) __half g_xwt[NROWS * FOUT];   // (XW)^T fp16 [f][j]

// ---------------- helpers ----------------
__device__ __forceinline__ uint32_t smem_u32(const void* p) {
    uint32_t a;
    asm("{ .reg .u64 t; cvta.to.shared.u64 t, %1; cvt.u32.u64 %0, t; }" : "=r"(a) : "l"(p));
    return a;
}

__device__ __forceinline__ void cp16(uint32_t sdst, const void* gsrc) {
    asm volatile("cp.async.cg.shared.global [%0], [%1], 16;" :: "r"(sdst), "l"(gsrc));
}
__device__ __forceinline__ void cp_commit() { asm volatile("cp.async.commit_group;" ::: "memory"); }
template <int N>
__device__ __forceinline__ void cp_wait() { asm volatile("cp.async.wait_group %0;" :: "n"(N) : "memory"); }

__device__ __forceinline__ void ldsm4(uint32_t* r, uint32_t addr) {
    asm volatile("ldmatrix.sync.aligned.m8n8.x4.shared.b16 {%0,%1,%2,%3}, [%4];"
                 : "=r"(r[0]), "=r"(r[1]), "=r"(r[2]), "=r"(r[3]) : "r"(addr));
}
__device__ __forceinline__ void ldsm4t(uint32_t* r, uint32_t addr) {
    asm volatile("ldmatrix.sync.aligned.m8n8.x4.trans.shared.b16 {%0,%1,%2,%3}, [%4];"
                 : "=r"(r[0]), "=r"(r[1]), "=r"(r[2]), "=r"(r[3]) : "r"(addr));
}

__device__ __forceinline__ void mma16816(float* c, const uint32_t* a, uint32_t b0, uint32_t b1) {
    asm volatile("mma.sync.aligned.m16n8k16.row.col.f32.f16.f16.f32 "
                 "{%0,%1,%2,%3}, {%4,%5,%6,%7}, {%8,%9}, {%0,%1,%2,%3};"
                 : "+f"(c[0]), "+f"(c[1]), "+f"(c[2]), "+f"(c[3])
                 : "r"(a[0]), "r"(a[1]), "r"(a[2]), "r"(a[3]), "r"(b0), "r"(b1));
}

__device__ __forceinline__ uint32_t pack_h2(float x, float y) {
    __half hx = __float2half_rn(x), hy = __float2half_rn(y);
    uint16_t ux = *reinterpret_cast<uint16_t*>(&hx);
    uint16_t uy = *reinterpret_cast<uint16_t*>(&hy);
    return (uint32_t)ux | ((uint32_t)uy << 16);
}

// Load [ROWS x 64] fp16 K-major tile (rows of 128B), SW128 swizzle, 256 threads.
template <int ROWS>
__device__ __forceinline__ void ldtile(uint32_t sdst, const __half* g,
                                       int row0, int k0, int ldk, int tid) {
    constexpr int CH = ROWS * 8 / 256;
#pragma unroll
    for (int p = 0; p < CH; ++p) {
        int idx = p * 256 + tid;
        int r = idx >> 3, ck = idx & 7;
        const char* src = (const char*)(g + (size_t)(row0 + r) * ldk + k0) + ck * 16;
        cp16(sdst + r * 128 + ((uint32_t)(ck ^ (r & 7)) << 4), src);
    }
}

// ---------------- prep kernels ----------------
__global__ void splitx_kernel(const float* __restrict__ X) {
    int stride = gridDim.x * blockDim.x;
    for (int idx = blockIdx.x * blockDim.x + threadIdx.x; idx < NROWS * FIN; idx += stride) {
        float v = X[idx];
        __half h = __float2half_rn(v);
        g_xh[idx] = h;
        g_xl[idx] = __float2half_rn(v - __half2float(h));
    }
}

__global__ void prepw_kernel(const float* __restrict__ W) {
    int idx = blockIdx.x * blockDim.x + threadIdx.x;   // idx = c*FOUT + f (coalesced read)
    if (idx < FIN * FOUT) {
        int c = idx / FOUT, f = idx % FOUT;
        float v = W[idx];
        __half h = __float2half_rn(v);
        g_wth[f * FIN + c] = h;
        g_wtl[f * FIN + c] = __float2half_rn(v - __half2float(h));
    }
}

// =====================================================================================
// GEMM1': D[f][j] = sum_c Wt[f][c] * X[j][c], 3 fp16 limb products (hh + hl + lh).
// M=512(f) x N=8192(j) x K=512(c). Tile 128x256x64, 2 stages, 256 threads (2m x 4n).
// Epilogue: round D to a SINGLE fp16 -> g_xwt (row-major [f][j]).
// =====================================================================================
#define G1_SAH   0
#define G1_SAL   16384
#define G1_SBH   32768
#define G1_SBL   65536
#define G1_STAGE 98304
#define G1_SMEM  (2 * G1_STAGE)
#define G1_NIT   (FIN / 64)

__global__ void __launch_bounds__(256, 1) gemm1_kernel() {
    extern __shared__ __align__(1024) char smem[];
    uint32_t sb = smem_u32(smem);
    int tid = threadIdx.x, lane = tid & 31, warp = tid >> 5;
    int wm = warp >> 2, wn = warp & 3;
    int n0 = blockIdx.x * 256;                 // j
    int m0 = blockIdx.y * 128;                 // f

    int lr = lane & 15, lc = lane >> 4;
    int sw = lr & 7;
    uint32_t aRow[4], bRow[4], chk[4];
#pragma unroll
    for (int mi = 0; mi < 4; ++mi) aRow[mi] = (wm * 64 + mi * 16 + lr) * 128;
#pragma unroll
    for (int ng = 0; ng < 4; ++ng) bRow[ng] = (wn * 64 + ng * 16 + lr) * 128;
#pragma unroll
    for (int kc = 0; kc < 4; ++kc) chk[kc] = (uint32_t)((2 * kc + lc) ^ sw) << 4;

    float c[4][8][4];
#pragma unroll
    for (int mi = 0; mi < 4; ++mi)
#pragma unroll
        for (int ni = 0; ni < 8; ++ni)
#pragma unroll
            for (int q = 0; q < 4; ++q) c[mi][ni][q] = 0.0f;

#pragma unroll
    for (int s = 0; s < 2; ++s) {
        uint32_t st = sb + s * G1_STAGE;
        int k0 = s * 64;
        ldtile<128>(st + G1_SAH, g_wth, m0, k0, FIN, tid);
        ldtile<128>(st + G1_SAL, g_wtl, m0, k0, FIN, tid);
        ldtile<256>(st + G1_SBH, g_xh, n0, k0, FIN, tid);
        ldtile<256>(st + G1_SBL, g_xl, n0, k0, FIN, tid);
        cp_commit();
    }

    for (int it = 0; it < G1_NIT; ++it) {
        int s = it & 1;
        uint32_t st = sb + s * G1_STAGE;
        cp_wait<1>();
        __syncthreads();
#pragma unroll
        for (int kc = 0; kc < 4; ++kc) {
            uint32_t ah[4][4], al[4][4];
#pragma unroll
            for (int mi = 0; mi < 4; ++mi) {
                ldsm4(ah[mi], st + G1_SAH + aRow[mi] + chk[kc]);
                ldsm4(al[mi], st + G1_SAL + aRow[mi] + chk[kc]);
            }
#pragma unroll
            for (int ng = 0; ng < 4; ++ng) {
                uint32_t bh[4], bl[4];
                ldsm4(bh, st + G1_SBH + bRow[ng] + chk[kc]);
                ldsm4(bl, st + G1_SBL + bRow[ng] + chk[kc]);
#pragma unroll
                for (int mi = 0; mi < 4; ++mi) {
                    mma16816(c[mi][ng * 2 + 0], ah[mi], bh[0], bh[2]);
                    mma16816(c[mi][ng * 2 + 1], ah[mi], bh[1], bh[3]);
                    mma16816(c[mi][ng * 2 + 0], ah[mi], bl[0], bl[2]);
                    mma16816(c[mi][ng * 2 + 1], ah[mi], bl[1], bl[3]);
                    mma16816(c[mi][ng * 2 + 0], al[mi], bh[0], bh[2]);
                    mma16816(c[mi][ng * 2 + 1], al[mi], bh[1], bh[3]);
                }
            }
        }
        __syncthreads();
        if (it + 2 < G1_NIT) {
            int k0 = (it + 2) * 64;
            ldtile<128>(st + G1_SAH, g_wth, m0, k0, FIN, tid);
            ldtile<128>(st + G1_SAL, g_wtl, m0, k0, FIN, tid);
            ldtile<256>(st + G1_SBH, g_xh, n0, k0, FIN, tid);
            ldtile<256>(st + G1_SBL, g_xl, n0, k0, FIN, tid);
        }
        cp_commit();
    }

    // Epilogue: write single fp16 (XW)^T [f][j]
    int fr = m0 + wm * 64 + (lane >> 2);
    int jc = n0 + wn * 64 + (lane & 3) * 2;
#pragma unroll
    for (int mi = 0; mi < 4; ++mi) {
        int fa = fr + mi * 16, fb = fa + 8;
#pragma unroll
        for (int ni = 0; ni < 8; ++ni) {
            int j = jc + ni * 8;
            *reinterpret_cast<uint32_t*>(g_xwt + (size_t)fa * NROWS + j) =
                pack_h2(c[mi][ni][0], c[mi][ni][1]);
            *reinterpret_cast<uint32_t*>(g_xwt + (size_t)fb * NROWS + j) =
                pack_h2(c[mi][ni][2], c[mi][ni][3]);
        }
    }
}

// =====================================================================================
// GEMM2: D[i][f] = sum_j adj[j][i] * xwt[f][j]; fused in-degree + norm + relu.
// A loaded directly from int32 adj via cp.async; in-kernel {0,1}->fp16 convert into a
// DOUBLE-BUFFERED [j][i] smem tile (AH[0/1]) so conversion of stage it+1 overlaps the
// HMMA stream of stage it (no barrier between MMAs and convert within an iteration).
// Degree accumulated during conversion. Tile 128x256x64, 3 stages, 256 threads.
// Grid 2(n) x 64(m) = 128 CTAs = one wave.
// =====================================================================================
#define G2_SAI   0            // int32 A stages: 3 x 32768
#define G2_SB    98304        // fp16 B stages:  3 x 32768
#define G2_SAH   196608       // fp16 converted A: 2 x 16384 (double buffer)
#define G2_SMEM  229376
#define G2_NIT   (NROWS / 64)

__global__ void __launch_bounds__(256, 1) gemm2_kernel(const int* __restrict__ adj,
                                                       float* __restrict__ out) {
    __shared__ int sdeg[128];
    extern __shared__ __align__(1024) char smem[];
    uint32_t sb = smem_u32(smem);
    int tid = threadIdx.x, lane = tid & 31, warp = tid >> 5;
    int wm = warp >> 2, wn = warp & 3;
    int n0 = blockIdx.x * 256;                 // f
    int m0 = blockIdx.y * 128;                 // i

    if (tid < 128) sdeg[tid] = 0;

    // B (xwt) ldmatrix addresses (non-trans), rows = f, 128B rows
    int lr = lane & 15, lc = lane >> 4;
    int sw = lr & 7;
    uint32_t bRow[4], chk[4];
#pragma unroll
    for (int ng = 0; ng < 4; ++ng) bRow[ng] = (wn * 64 + ng * 16 + lr) * 128;
#pragma unroll
    for (int kc = 0; kc < 4; ++kc) chk[kc] = (uint32_t)((2 * kc + lc) ^ sw) << 4;

    // A trans-ldmatrix addresses: smem tile S[j][i], 256B rows, chunk swizzle ci^(j&7).
    int jb   = ((lane >> 4) & 1) * 8 + (lane & 7);   // row within 16-j window
    int icof = ((lane >> 3) & 1) * 8;                // +8 i for groups 1 and 3
    uint32_t aAddr[4];
#pragma unroll
    for (int mi = 0; mi < 4; ++mi) {
        int ic = wm * 64 + mi * 16 + icof;
        int ci = ic >> 3;
        aAddr[mi] = (uint32_t)(jb * 256 + ((ci ^ (lane & 7)) << 4));
    }

    // conversion assignment: thread -> 4 i-columns x 8 j-rows per tile
    int cv_i4 = (tid & 31) * 4;
    int cv_jb = (tid >> 5) * 8;
    int cv_ci = cv_i4 >> 3;
    int d0 = 0, d1 = 0, d2 = 0, d3 = 0;

    float c[4][8][4];
#pragma unroll
    for (int mi = 0; mi < 4; ++mi)
#pragma unroll
        for (int ni = 0; ni < 8; ++ni)
#pragma unroll
            for (int q = 0; q < 4; ++q) c[mi][ni][q] = 0.0f;

    // prefetch 3 stages: int A tile [64 x 128] int32 (512B rows) + fp16 B tile
#pragma unroll
    for (int s = 0; s < 3; ++s) {
        int k0 = s * 64;
#pragma unroll
        for (int p = 0; p < 8; ++p) {
            int idx = p * 256 + tid;
            int r = idx >> 5, ck = idx & 31;
            cp16(sb + G2_SAI + s * 32768 + r * 512 + ck * 16,
                 adj + (size_t)(k0 + r) * NROWS + m0 + ck * 4);
        }
        ldtile<256>(sb + G2_SB + s * 32768, g_xwt, n0, k0, NROWS, tid);
        cp_commit();
    }

    // prologue: convert stage 0 into AH[0]
    cp_wait<1>();
    __syncthreads();
    {
        const char* srcb = smem + G2_SAI + 0 * 32768 + cv_i4 * 4;
        char* dstb = smem + G2_SAH + 0 * 16384 + (cv_i4 & 7) * 2;
#pragma unroll
        for (int jj = 0; jj < 8; ++jj) {
            int j = cv_jb + jj;
            int4 v = *reinterpret_cast<const int4*>(srcb + j * 512);
            uint32_t p01 = (uint32_t)(v.x | (v.y << 16)) * 0x3C00u;
            uint32_t p23 = (uint32_t)(v.z | (v.w << 16)) * 0x3C00u;
            d0 += v.x; d1 += v.y; d2 += v.z; d3 += v.w;
            uint2 pv; pv.x = p01; pv.y = p23;
            *reinterpret_cast<uint2*>(dstb + j * 256 + ((cv_ci ^ (j & 7)) << 4)) = pv;
        }
    }

    for (int it = 0; it < G2_NIT; ++it) {
        int s = it % 3;
        cp_wait<1>();
        __syncthreads();   // orders: prev convert writes, cp.async data, prev-iter smem reads

        // ---- compute from AH[it&1] + B stage s ----
        uint32_t sta = sb + G2_SAH + (uint32_t)(it & 1) * 16384;
        uint32_t stb = sb + G2_SB + s * 32768;
#pragma unroll
        for (int kc = 0; kc < 4; ++kc) {
            uint32_t a[4][4];
#pragma unroll
            for (int mi = 0; mi < 4; ++mi)
                ldsm4t(a[mi], sta + kc * 4096 + aAddr[mi]);
#pragma unroll
            for (int ng = 0; ng < 4; ++ng) {
                uint32_t b[4];
                ldsm4(b, stb + bRow[ng] + chk[kc]);
#pragma unroll
                for (int mi = 0; mi < 4; ++mi) {
                    mma16816(c[mi][ng * 2 + 0], a[mi], b[0], b[2]);
                    mma16816(c[mi][ng * 2 + 1], a[mi], b[1], b[3]);
                }
            }
        }

        // ---- convert stage it+1 -> AH[(it+1)&1]  (overlaps other warps' MMAs) ----
        if (it + 1 < G2_NIT) {
            const char* srcb = smem + G2_SAI + ((it + 1) % 3) * 32768 + cv_i4 * 4;
            char* dstb = smem + G2_SAH + (uint32_t)((it + 1) & 1) * 16384 + (cv_i4 & 7) * 2;
#pragma unroll
            for (int jj = 0; jj < 8; ++jj) {
                int j = cv_jb + jj;
                int4 v = *reinterpret_cast<const int4*>(srcb + j * 512);
                uint32_t p01 = (uint32_t)(v.x | (v.y << 16)) * 0x3C00u;
                uint32_t p23 = (uint32_t)(v.z | (v.w << 16)) * 0x3C00u;
                d0 += v.x; d1 += v.y; d2 += v.z; d3 += v.w;
                uint2 pv; pv.x = p01; pv.y = p23;
                *reinterpret_cast<uint2*>(dstb + j * 256 + ((cv_ci ^ (j & 7)) << 4)) = pv;
            }
        }
        __syncthreads();

        // ---- prefetch it+3 into just-freed stage ----
        if (it + 3 < G2_NIT) {
            int k0 = (it + 3) * 64;
#pragma unroll
            for (int p = 0; p < 8; ++p) {
                int idx = p * 256 + tid;
                int r = idx >> 5, ck = idx & 31;
                cp16(sb + G2_SAI + s * 32768 + r * 512 + ck * 16,
                     adj + (size_t)(k0 + r) * NROWS + m0 + ck * 4);
            }
            ldtile<256>(sb + G2_SB + s * 32768, g_xwt, n0, k0, NROWS, tid);
        }
        cp_commit();
    }

    // ---- degree reduce -> norm ----
    atomicAdd(&sdeg[cv_i4 + 0], d0);
    atomicAdd(&sdeg[cv_i4 + 1], d1);
    atomicAdd(&sdeg[cv_i4 + 2], d2);
    atomicAdd(&sdeg[cv_i4 + 3], d3);
    __syncthreads();

    // ---- epilogue: out[i][f] = relu(c * rsqrt(max(deg,1))) ----
    int il = wm * 64 + (lane >> 2);
    int fc = n0 + wn * 64 + (lane & 3) * 2;
#pragma unroll
    for (int mi = 0; mi < 4; ++mi) {
        int ial = il + mi * 16, ibl = ial + 8;
        float na = rsqrtf(fmaxf((float)sdeg[ial], 1.0f));
        float nb = rsqrtf(fmaxf((float)sdeg[ibl], 1.0f));
        float* oa = out + (size_t)(m0 + ial) * FOUT;
        float* ob = out + (size_t)(m0 + ibl) * FOUT;
#pragma unroll
        for (int ni = 0; ni < 8; ++ni) {
            int f = fc + ni * 8;
            float2 va, vb;
            va.x = fmaxf(c[mi][ni][0] * na, 0.0f);
            va.y = fmaxf(c[mi][ni][1] * na, 0.0f);
            vb.x = fmaxf(c[mi][ni][2] * nb, 0.0f);
            vb.y = fmaxf(c[mi][ni][3] * nb, 0.0f);
            *reinterpret_cast<float2*>(oa + f) = va;
            *reinterpret_cast<float2*>(ob + f) = vb;
        }
    }
}

// ---------------- launch ----------------
extern "C" void kernel_launch(void* const* d_in, const int* in_sizes, int n_in,
                              void* d_out, int out_size) {
    const float* X   = (const float*)d_in[0];
    const int*   adj = (const int*)d_in[1];
    const float* W   = (const float*)d_in[2];
    float*       out = (float*)d_out;

    cudaFuncSetAttribute(gemm1_kernel, cudaFuncAttributeMaxDynamicSharedMemorySize, G1_SMEM);
    cudaFuncSetAttribute(gemm2_kernel, cudaFuncAttributeMaxDynamicSharedMemorySize, G2_SMEM);

    splitx_kernel<<<1024, 256>>>(X);
    prepw_kernel<<<(FIN * FOUT + 255) / 256, 256>>>(W);

    gemm1_kernel<<<dim3(NROWS / 256, FIN / 128), 256, G1_SMEM>>>();
    gemm2_kernel<<<dim3(FOUT / 256, NROWS / 128), 256, G2_SMEM>>>(adj, out);
}

// round 14
// speedup vs baseline: 1.7849x; 1.0145x over previous
#include <cuda_runtime.h>
#include <cuda_fp16.h>
#include <cstdint>
#include <cstddef>

#define NROWS 8192
#define FIN   512
#define FOUT  512

// ---------------- scratch (device globals; no allocations allowed) ----------------
__device__ __align__(1024) __half g_xh[NROWS * FIN];     // X hi limb  [j][c]
__device__ __align__(1024) __half g_xl[NROWS * FIN];     // X lo limb
__device__ __align__(1024) __half g_wth[FIN * FOUT];     // W^T hi [f][c]
__device__ __align__(1024) __half g_wtl[FIN * FOUT];     // W^T lo
__device__ __align__(1024) __half g_xwt[NROWS * FOUT];   // (XW)^T fp16 [f][j]

// ---------------- helpers ----------------
__device__ __forceinline__ uint32_t smem_u32(const void* p) {
    uint32_t a;
    asm("{ .reg .u64 t; cvta.to.shared.u64 t, %1; cvt.u32.u64 %0, t; }" : "=r"(a) : "l"(p));
    return a;
}

__device__ __forceinline__ void cp16(uint32_t sdst, const void* gsrc) {
    asm volatile("cp.async.cg.shared.global [%0], [%1], 16;" :: "r"(sdst), "l"(gsrc));
}
__device__ __forceinline__ void cp_commit() { asm volatile("cp.async.commit_group;" ::: "memory"); }
template <int N>
__device__ __forceinline__ void cp_wait() { asm volatile("cp.async.wait_group %0;" :: "n"(N) : "memory"); }

__device__ __forceinline__ void ldsm4(uint32_t* r, uint32_t addr) {
    asm volatile("ldmatrix.sync.aligned.m8n8.x4.shared.b16 {%0,%1,%2,%3}, [%4];"
                 : "=r"(r[0]), "=r"(r[1]), "=r"(r[2]), "=r"(r[3]) : "r"(addr));
}
__device__ __forceinline__ void ldsm4t(uint32_t* r, uint32_t addr) {
    asm volatile("ldmatrix.sync.aligned.m8n8.x4.trans.shared.b16 {%0,%1,%2,%3}, [%4];"
                 : "=r"(r[0]), "=r"(r[1]), "=r"(r[2]), "=r"(r[3]) : "r"(addr));
}

__device__ __forceinline__ void mma16816(float* c, const uint32_t* a, uint32_t b0, uint32_t b1) {
    asm volatile("mma.sync.aligned.m16n8k16.row.col.f32.f16.f16.f32 "
                 "{%0,%1,%2,%3}, {%4,%5,%6,%7}, {%8,%9}, {%0,%1,%2,%3};"
                 : "+f"(c[0]), "+f"(c[1]), "+f"(c[2]), "+f"(c[3])
                 : "r"(a[0]), "r"(a[1]), "r"(a[2]), "r"(a[3]), "r"(b0), "r"(b1));
}

__device__ __forceinline__ uint32_t pack_h2(float x, float y) {
    __half hx = __float2half_rn(x), hy = __float2half_rn(y);
    uint16_t ux = *reinterpret_cast<uint16_t*>(&hx);
    uint16_t uy = *reinterpret_cast<uint16_t*>(&hy);
    return (uint32_t)ux | ((uint32_t)uy << 16);
}

// Load [ROWS x 64] fp16 K-major tile (rows of 128B), SW128 swizzle, NT threads.
template <int ROWS, int NT>
__device__ __forceinline__ void ldtile(uint32_t sdst, const __half* g,
                                       int row0, int k0, int ldk, int tid) {
    constexpr int CH = ROWS * 8 / NT;
#pragma unroll
    for (int p = 0; p < CH; ++p) {
        int idx = p * NT + tid;
        int r = idx >> 3, ck = idx & 7;
        const char* src = (const char*)(g + (size_t)(row0 + r) * ldk + k0) + ck * 16;
        cp16(sdst + r * 128 + ((uint32_t)(ck ^ (r & 7)) << 4), src);
    }
}

// ---------------- prep kernels ----------------
__global__ void splitx_kernel(const float* __restrict__ X) {
    int stride = gridDim.x * blockDim.x;
    for (int idx = blockIdx.x * blockDim.x + threadIdx.x; idx < NROWS * FIN; idx += stride) {
        float v = X[idx];
        __half h = __float2half_rn(v);
        g_xh[idx] = h;
        g_xl[idx] = __float2half_rn(v - __half2float(h));
    }
}

__global__ void prepw_kernel(const float* __restrict__ W) {
    int idx = blockIdx.x * blockDim.x + threadIdx.x;   // idx = c*FOUT + f (coalesced read)
    if (idx < FIN * FOUT) {
        int c = idx / FOUT, f = idx % FOUT;
        float v = W[idx];
        __half h = __float2half_rn(v);
        g_wth[f * FIN + c] = h;
        g_wtl[f * FIN + c] = __float2half_rn(v - __half2float(h));
    }
}

// =====================================================================================
// GEMM1': D[f][j] = sum_c Wt[f][c] * X[j][c], 3 fp16 limb products (hh + hl + lh).
// M=512(f) x N=8192(j) x K=512(c). Tile 128x256x64, 2 stages, 256 threads (2m x 4n).
// Epilogue: round D to a SINGLE fp16 -> g_xwt (row-major [f][j]).
// =====================================================================================
#define G1_SAH   0
#define G1_SAL   16384
#define G1_SBH   32768
#define G1_SBL   65536
#define G1_STAGE 98304
#define G1_SMEM  (2 * G1_STAGE)
#define G1_NIT   (FIN / 64)

__global__ void __launch_bounds__(256, 1) gemm1_kernel() {
    extern __shared__ __align__(1024) char smem[];
    uint32_t sb = smem_u32(smem);
    int tid = threadIdx.x, lane = tid & 31, warp = tid >> 5;
    int wm = warp >> 2, wn = warp & 3;
    int n0 = blockIdx.x * 256;                 // j
    int m0 = blockIdx.y * 128;                 // f

    int lr = lane & 15, lc = lane >> 4;
    int sw = lr & 7;
    uint32_t aRow[4], bRow[4], chk[4];
#pragma unroll
    for (int mi = 0; mi < 4; ++mi) aRow[mi] = (wm * 64 + mi * 16 + lr) * 128;
#pragma unroll
    for (int ng = 0; ng < 4; ++ng) bRow[ng] = (wn * 64 + ng * 16 + lr) * 128;
#pragma unroll
    for (int kc = 0; kc < 4; ++kc) chk[kc] = (uint32_t)((2 * kc + lc) ^ sw) << 4;

    float c[4][8][4];
#pragma unroll
    for (int mi = 0; mi < 4; ++mi)
#pragma unroll
        for (int ni = 0; ni < 8; ++ni)
#pragma unroll
            for (int q = 0; q < 4; ++q) c[mi][ni][q] = 0.0f;

#pragma unroll
    for (int s = 0; s < 2; ++s) {
        uint32_t st = sb + s * G1_STAGE;
        int k0 = s * 64;
        ldtile<128, 256>(st + G1_SAH, g_wth, m0, k0, FIN, tid);
        ldtile<128, 256>(st + G1_SAL, g_wtl, m0, k0, FIN, tid);
        ldtile<256, 256>(st + G1_SBH, g_xh, n0, k0, FIN, tid);
        ldtile<256, 256>(st + G1_SBL, g_xl, n0, k0, FIN, tid);
        cp_commit();
    }

    for (int it = 0; it < G1_NIT; ++it) {
        int s = it & 1;
        uint32_t st = sb + s * G1_STAGE;
        cp_wait<1>();
        __syncthreads();
#pragma unroll
        for (int kc = 0; kc < 4; ++kc) {
            uint32_t ah[4][4], al[4][4];
#pragma unroll
            for (int mi = 0; mi < 4; ++mi) {
                ldsm4(ah[mi], st + G1_SAH + aRow[mi] + chk[kc]);
                ldsm4(al[mi], st + G1_SAL + aRow[mi] + chk[kc]);
            }
#pragma unroll
            for (int ng = 0; ng < 4; ++ng) {
                uint32_t bh[4], bl[4];
                ldsm4(bh, st + G1_SBH + bRow[ng] + chk[kc]);
                ldsm4(bl, st + G1_SBL + bRow[ng] + chk[kc]);
#pragma unroll
                for (int mi = 0; mi < 4; ++mi) {
                    mma16816(c[mi][ng * 2 + 0], ah[mi], bh[0], bh[2]);
                    mma16816(c[mi][ng * 2 + 1], ah[mi], bh[1], bh[3]);
                    mma16816(c[mi][ng * 2 + 0], ah[mi], bl[0], bl[2]);
                    mma16816(c[mi][ng * 2 + 1], ah[mi], bl[1], bl[3]);
                    mma16816(c[mi][ng * 2 + 0], al[mi], bh[0], bh[2]);
                    mma16816(c[mi][ng * 2 + 1], al[mi], bh[1], bh[3]);
                }
            }
        }
        __syncthreads();
        if (it + 2 < G1_NIT) {
            int k0 = (it + 2) * 64;
            ldtile<128, 256>(st + G1_SAH, g_wth, m0, k0, FIN, tid);
            ldtile<128, 256>(st + G1_SAL, g_wtl, m0, k0, FIN, tid);
            ldtile<256, 256>(st + G1_SBH, g_xh, n0, k0, FIN, tid);
            ldtile<256, 256>(st + G1_SBL, g_xl, n0, k0, FIN, tid);
        }
        cp_commit();
    }

    // Epilogue: write single fp16 (XW)^T [f][j]
    int fr = m0 + wm * 64 + (lane >> 2);
    int jc = n0 + wn * 64 + (lane & 3) * 2;
#pragma unroll
    for (int mi = 0; mi < 4; ++mi) {
        int fa = fr + mi * 16, fb = fa + 8;
#pragma unroll
        for (int ni = 0; ni < 8; ++ni) {
            int j = jc + ni * 8;
            *reinterpret_cast<uint32_t*>(g_xwt + (size_t)fa * NROWS + j) =
                pack_h2(c[mi][ni][0], c[mi][ni][1]);
            *reinterpret_cast<uint32_t*>(g_xwt + (size_t)fb * NROWS + j) =
                pack_h2(c[mi][ni][2], c[mi][ni][3]);
        }
    }
}

// =====================================================================================
// GEMM2: D[i][f] = sum_j adj[j][i] * xwt[f][j]; fused in-degree + norm + relu.
// 512 threads (16 warps, 2m x 8n: each warp 64i x 32f) -> 4 warps/SMSP to cover
// ldsm->mma and accumulator RAW gaps (R13 was issue-starved at 2 warps/SMSP).
// A loaded directly from int32 adj via cp.async; {0,1}->fp16 convert into a
// double-buffered [j][i] smem tile; degree fused. Tile 128x256x64, 3 stages.
// Grid 2(n) x 64(m) = 128 CTAs = one wave.
// =====================================================================================
#define G2_SAI   0            // int32 A stages: 3 x 32768
#define G2_SB    98304        // fp16 B stages:  3 x 32768
#define G2_SAH   196608       // fp16 converted A: 2 x 16384 (double buffer)
#define G2_SMEM  229376
#define G2_NIT   (NROWS / 64)

__global__ void __launch_bounds__(512, 1) gemm2_kernel(const int* __restrict__ adj,
                                                       float* __restrict__ out) {
    __shared__ int sdeg[128];
    extern __shared__ __align__(1024) char smem[];
    uint32_t sb = smem_u32(smem);
    int tid = threadIdx.x, lane = tid & 31, warp = tid >> 5;
    int wm = warp >> 3, wn = warp & 7;         // 2m x 8n warp grid
    int n0 = blockIdx.x * 256;                 // f
    int m0 = blockIdx.y * 128;                 // i

    if (tid < 128) sdeg[tid] = 0;

    // B (xwt) ldmatrix addresses (non-trans), rows = f, 128B rows
    int lr = lane & 15, lc = lane >> 4;
    int sw = lr & 7;
    uint32_t bRow[2], chk[4];
#pragma unroll
    for (int ng = 0; ng < 2; ++ng) bRow[ng] = (wn * 32 + ng * 16 + lr) * 128;
#pragma unroll
    for (int kc = 0; kc < 4; ++kc) chk[kc] = (uint32_t)((2 * kc + lc) ^ sw) << 4;

    // A trans-ldmatrix addresses: smem tile S[j][i], 256B rows, chunk swizzle ci^(j&7).
    int jb   = ((lane >> 4) & 1) * 8 + (lane & 7);   // row within 16-j window
    int icof = ((lane >> 3) & 1) * 8;                // +8 i for groups 1 and 3
    uint32_t aAddr[4];
#pragma unroll
    for (int mi = 0; mi < 4; ++mi) {
        int ic = wm * 64 + mi * 16 + icof;
        int ci = ic >> 3;
        aAddr[mi] = (uint32_t)(jb * 256 + ((ci ^ (lane & 7)) << 4));
    }

    // conversion assignment: thread -> 4 i-columns x 4 j-rows per tile (512 threads)
    int cv_i4 = (tid & 31) * 4;
    int cv_jb = (tid >> 5) * 4;
    int cv_ci = cv_i4 >> 3;
    int d0 = 0, d1 = 0, d2 = 0, d3 = 0;

    float c[4][4][4];
#pragma unroll
    for (int mi = 0; mi < 4; ++mi)
#pragma unroll
        for (int ni = 0; ni < 4; ++ni)
#pragma unroll
            for (int q = 0; q < 4; ++q) c[mi][ni][q] = 0.0f;

    // prefetch 3 stages: int A tile [64 x 128] int32 (512B rows) + fp16 B tile
#pragma unroll
    for (int s = 0; s < 3; ++s) {
        int k0 = s * 64;
#pragma unroll
        for (int p = 0; p < 4; ++p) {
            int idx = p * 512 + tid;
            int r = idx >> 5, ck = idx & 31;
            cp16(sb + G2_SAI + s * 32768 + r * 512 + ck * 16,
                 adj + (size_t)(k0 + r) * NROWS + m0 + ck * 4);
        }
        ldtile<256, 512>(sb + G2_SB + s * 32768, g_xwt, n0, k0, NROWS, tid);
        cp_commit();
    }

    // prologue: convert stage 0 into AH[0]
    cp_wait<1>();
    __syncthreads();
    {
        const char* srcb = smem + G2_SAI + 0 * 32768 + cv_i4 * 4;
        char* dstb = smem + G2_SAH + 0 * 16384 + (cv_i4 & 7) * 2;
#pragma unroll
        for (int jj = 0; jj < 4; ++jj) {
            int j = cv_jb + jj;
            int4 v = *reinterpret_cast<const int4*>(srcb + j * 512);
            uint32_t p01 = (uint32_t)(v.x | (v.y << 16)) * 0x3C00u;
            uint32_t p23 = (uint32_t)(v.z | (v.w << 16)) * 0x3C00u;
            d0 += v.x; d1 += v.y; d2 += v.z; d3 += v.w;
            uint2 pv; pv.x = p01; pv.y = p23;
            *reinterpret_cast<uint2*>(dstb + j * 256 + ((cv_ci ^ (j & 7)) << 4)) = pv;
        }
    }

    for (int it = 0; it < G2_NIT; ++it) {
        int s = it % 3;
        cp_wait<1>();
        __syncthreads();   // orders: prev convert writes, cp.async data, prev-iter smem reads

        // ---- compute from AH[it&1] + B stage s ----
        uint32_t sta = sb + G2_SAH + (uint32_t)(it & 1) * 16384;
        uint32_t stb = sb + G2_SB + s * 32768;
#pragma unroll
        for (int kc = 0; kc < 4; ++kc) {
            uint32_t a[4][4];
#pragma unroll
            for (int mi = 0; mi < 4; ++mi)
                ldsm4t(a[mi], sta + kc * 4096 + aAddr[mi]);
#pragma unroll
            for (int ng = 0; ng < 2; ++ng) {
                uint32_t b[4];
                ldsm4(b, stb + bRow[ng] + chk[kc]);
#pragma unroll
                for (int mi = 0; mi < 4; ++mi) {
                    mma16816(c[mi][ng * 2 + 0], a[mi], b[0], b[2]);
                    mma16816(c[mi][ng * 2 + 1], a[mi], b[1], b[3]);
                }
            }
        }

        // ---- convert stage it+1 -> AH[(it+1)&1]  (overlaps other warps' MMAs) ----
        if (it + 1 < G2_NIT) {
            const char* srcb = smem + G2_SAI + ((it + 1) % 3) * 32768 + cv_i4 * 4;
            char* dstb = smem + G2_SAH + (uint32_t)((it + 1) & 1) * 16384 + (cv_i4 & 7) * 2;
#pragma unroll
            for (int jj = 0; jj < 4; ++jj) {
                int j = cv_jb + jj;
                int4 v = *reinterpret_cast<const int4*>(srcb + j * 512);
                uint32_t p01 = (uint32_t)(v.x | (v.y << 16)) * 0x3C00u;
                uint32_t p23 = (uint32_t)(v.z | (v.w << 16)) * 0x3C00u;
                d0 += v.x; d1 += v.y; d2 += v.z; d3 += v.w;
                uint2 pv; pv.x = p01; pv.y = p23;
                *reinterpret_cast<uint2*>(dstb + j * 256 + ((cv_ci ^ (j & 7)) << 4)) = pv;
            }
        }
        __syncthreads();

        // ---- prefetch it+3 into just-freed stage ----
        if (it + 3 < G2_NIT) {
            int k0 = (it + 3) * 64;
#pragma unroll
            for (int p = 0; p < 4; ++p) {
                int idx = p * 512 + tid;
                int r = idx >> 5, ck = idx & 31;
                cp16(sb + G2_SAI + s * 32768 + r * 512 + ck * 16,
                     adj + (size_t)(k0 + r) * NROWS + m0 + ck * 4);
            }
            ldtile<256, 512>(sb + G2_SB + s * 32768, g_xwt, n0, k0, NROWS, tid);
        }
        cp_commit();
    }

    // ---- degree reduce -> norm ----
    atomicAdd(&sdeg[cv_i4 + 0], d0);
    atomicAdd(&sdeg[cv_i4 + 1], d1);
    atomicAdd(&sdeg[cv_i4 + 2], d2);
    atomicAdd(&sdeg[cv_i4 + 3], d3);
    __syncthreads();

    // ---- epilogue: out[i][f] = relu(c * rsqrt(max(deg,1))) ----
    int il = wm * 64 + (lane >> 2);
    int fc = n0 + wn * 32 + (lane & 3) * 2;
#pragma unroll
    for (int mi = 0; mi < 4; ++mi) {
        int ial = il + mi * 16, ibl = ial + 8;
        float na = rsqrtf(fmaxf((float)sdeg[ial], 1.0f));
        float nb = rsqrtf(fmaxf((float)sdeg[ibl], 1.0f));
        float* oa = out + (size_t)(m0 + ial) * FOUT;
        float* ob = out + (size_t)(m0 + ibl) * FOUT;
#pragma unroll
        for (int ni = 0; ni < 4; ++ni) {
            int f = fc + ni * 8;
            float2 va, vb;
            va.x = fmaxf(c[mi][ni][0] * na, 0.0f);
            va.y = fmaxf(c[mi][ni][1] * na, 0.0f);
            vb.x = fmaxf(c[mi][ni][2] * nb, 0.0f);
            vb.y = fmaxf(c[mi][ni][3] * nb, 0.0f);
            *reinterpret_cast<float2*>(oa + f) = va;
            *reinterpret_cast<float2*>(ob + f) = vb;
        }
    }
}

// ---------------- launch ----------------
extern "C" void kernel_launch(void* const* d_in, const int* in_sizes, int n_in,
                              void* d_out, int out_size) {
    const float* X   = (const float*)d_in[0];
    const int*   adj = (const int*)d_in[1];
    const float* W   = (const float*)d_in[2];
    float*       out = (float*)d_out;

    cudaFuncSetAttribute(gemm1_kernel, cudaFuncAttributeMaxDynamicSharedMemorySize, G1_SMEM);
    cudaFuncSetAttribute(gemm2_kernel, cudaFuncAttributeMaxDynamicSharedMemorySize, G2_SMEM);

    splitx_kernel<<<1024, 256>>>(X);
    prepw_kernel<<<(FIN * FOUT + 255) / 256, 256>>>(W);

    gemm1_kernel<<<dim3(NROWS / 256, FIN / 128), 256, G1_SMEM>>>();
    gemm2_kernel<<<dim3(FOUT / 256, NROWS / 128), 512, G2_SMEM>>>(adj, out);
}

// round 15
// speedup vs baseline: 1.8705x; 1.0479x over previous
#include <cuda_runtime.h>
#include <cuda_fp16.h>
#include <cstdint>
#include <cstddef>

#define NROWS 8192
#define FIN   512
#define FOUT  512

// ---------------- scratch (device globals; no allocations allowed) ----------------
__device__ __align__(1024) __half g_xh[NROWS * FIN];     // X hi limb  [j][c]
__device__ __align__(1024) __half g_xl[NROWS * FIN];     // X lo limb
__device__ __align__(1024) __half g_wt[FIN * FOUT];      // W^T fp16 [f][c]
__device__ __align__(1024) __half g_xwt[NROWS * FOUT];   // (XW)^T fp16 [f][j]

// ---------------- helpers ----------------
__device__ __forceinline__ uint32_t smem_u32(const void* p) {
    uint32_t a;
    asm("{ .reg .u64 t; cvta.to.shared.u64 t, %1; cvt.u32.u64 %0, t; }" : "=r"(a) : "l"(p));
    return a;
}

__device__ __forceinline__ void cp16(uint32_t sdst, const void* gsrc) {
    asm volatile("cp.async.cg.shared.global [%0], [%1], 16;" :: "r"(sdst), "l"(gsrc));
}
__device__ __forceinline__ void cp_commit() { asm volatile("cp.async.commit_group;" ::: "memory"); }
template <int N>
__device__ __forceinline__ void cp_wait() { asm volatile("cp.async.wait_group %0;" :: "n"(N) : "memory"); }

__device__ __forceinline__ void ldsm4(uint32_t* r, uint32_t addr) {
    asm volatile("ldmatrix.sync.aligned.m8n8.x4.shared.b16 {%0,%1,%2,%3}, [%4];"
                 : "=r"(r[0]), "=r"(r[1]), "=r"(r[2]), "=r"(r[3]) : "r"(addr));
}
__device__ __forceinline__ void ldsm4t(uint32_t* r, uint32_t addr) {
    asm volatile("ldmatrix.sync.aligned.m8n8.x4.trans.shared.b16 {%0,%1,%2,%3}, [%4];"
                 : "=r"(r[0]), "=r"(r[1]), "=r"(r[2]), "=r"(r[3]) : "r"(addr));
}

__device__ __forceinline__ void mma16816(float* c, const uint32_t* a, uint32_t b0, uint32_t b1) {
    asm volatile("mma.sync.aligned.m16n8k16.row.col.f32.f16.f16.f32 "
                 "{%0,%1,%2,%3}, {%4,%5,%6,%7}, {%8,%9}, {%0,%1,%2,%3};"
                 : "+f"(c[0]), "+f"(c[1]), "+f"(c[2]), "+f"(c[3])
                 : "r"(a[0]), "r"(a[1]), "r"(a[2]), "r"(a[3]), "r"(b0), "r"(b1));
}

__device__ __forceinline__ uint32_t pack_h2(float x, float y) {
    __half hx = __float2half_rn(x), hy = __float2half_rn(y);
    uint16_t ux = *reinterpret_cast<uint16_t*>(&hx);
    uint16_t uy = *reinterpret_cast<uint16_t*>(&hy);
    return (uint32_t)ux | ((uint32_t)uy << 16);
}

// Load [ROWS x 64] fp16 K-major tile (rows of 128B), SW128 swizzle, NT threads.
template <int ROWS, int NT>
__device__ __forceinline__ void ldtile(uint32_t sdst, const __half* g,
                                       int row0, int k0, int ldk, int tid) {
    constexpr int CH = ROWS * 8 / NT;
#pragma unroll
    for (int p = 0; p < CH; ++p) {
        int idx = p * NT + tid;
        int r = idx >> 3, ck = idx & 7;
        const char* src = (const char*)(g + (size_t)(row0 + r) * ldk + k0) + ck * 16;
        cp16(sdst + r * 128 + ((uint32_t)(ck ^ (r & 7)) << 4), src);
    }
}

// ---------------- prep kernels ----------------
__global__ void splitx_kernel(const float* __restrict__ X) {
    int stride = gridDim.x * blockDim.x;
    for (int idx = blockIdx.x * blockDim.x + threadIdx.x; idx < NROWS * FIN; idx += stride) {
        float v = X[idx];
        __half h = __float2half_rn(v);
        g_xh[idx] = h;
        g_xl[idx] = __float2half_rn(v - __half2float(h));
    }
}

__global__ void prepw_kernel(const float* __restrict__ W) {
    int idx = blockIdx.x * blockDim.x + threadIdx.x;   // idx = c*FOUT + f (coalesced read)
    if (idx < FIN * FOUT) {
        int c = idx / FOUT, f = idx % FOUT;
        g_wt[f * FIN + c] = __float2half_rn(W[idx]);
    }
}

// =====================================================================================
// GEMM1': D[f][j] = sum_c Wt[f][c] * X[j][c], 2 products (wh*xh + wh*xl).
// M=512(f) x N=8192(j) x K=512(c). Tile 128x256x64, 2 stages, 256 threads (2m x 4n).
// Epilogue: round D to a SINGLE fp16 -> g_xwt (row-major [f][j]).
// =====================================================================================
#define G1_SA    0
#define G1_SBH   16384
#define G1_SBL   49152
#define G1_STAGE 81920
#define G1_SMEM  (2 * G1_STAGE)
#define G1_NIT   (FIN / 64)

__global__ void __launch_bounds__(256, 1) gemm1_kernel() {
    extern __shared__ __align__(1024) char smem[];
    uint32_t sb = smem_u32(smem);
    int tid = threadIdx.x, lane = tid & 31, warp = tid >> 5;
    int wm = warp >> 2, wn = warp & 3;
    int n0 = blockIdx.x * 256;                 // j
    int m0 = blockIdx.y * 128;                 // f

    int lr = lane & 15, lc = lane >> 4;
    int sw = lr & 7;
    uint32_t aRow[4], bRow[4], chk[4];
#pragma unroll
    for (int mi = 0; mi < 4; ++mi) aRow[mi] = (wm * 64 + mi * 16 + lr) * 128;
#pragma unroll
    for (int ng = 0; ng < 4; ++ng) bRow[ng] = (wn * 64 + ng * 16 + lr) * 128;
#pragma unroll
    for (int kc = 0; kc < 4; ++kc) chk[kc] = (uint32_t)((2 * kc + lc) ^ sw) << 4;

    float c[4][8][4];
#pragma unroll
    for (int mi = 0; mi < 4; ++mi)
#pragma unroll
        for (int ni = 0; ni < 8; ++ni)
#pragma unroll
            for (int q = 0; q < 4; ++q) c[mi][ni][q] = 0.0f;

#pragma unroll
    for (int s = 0; s < 2; ++s) {
        uint32_t st = sb + s * G1_STAGE;
        int k0 = s * 64;
        ldtile<128, 256>(st + G1_SA, g_wt, m0, k0, FIN, tid);
        ldtile<256, 256>(st + G1_SBH, g_xh, n0, k0, FIN, tid);
        ldtile<256, 256>(st + G1_SBL, g_xl, n0, k0, FIN, tid);
        cp_commit();
    }

    for (int it = 0; it < G1_NIT; ++it) {
        int s = it & 1;
        uint32_t st = sb + s * G1_STAGE;
        cp_wait<1>();
        __syncthreads();
#pragma unroll
        for (int kc = 0; kc < 4; ++kc) {
            uint32_t ah[4][4];
#pragma unroll
            for (int mi = 0; mi < 4; ++mi)
                ldsm4(ah[mi], st + G1_SA + aRow[mi] + chk[kc]);
#pragma unroll
            for (int ng = 0; ng < 4; ++ng) {
                uint32_t bh[4], bl[4];
                ldsm4(bh, st + G1_SBH + bRow[ng] + chk[kc]);
                ldsm4(bl, st + G1_SBL + bRow[ng] + chk[kc]);
#pragma unroll
                for (int mi = 0; mi < 4; ++mi) {
                    mma16816(c[mi][ng * 2 + 0], ah[mi], bh[0], bh[2]);
                    mma16816(c[mi][ng * 2 + 1], ah[mi], bh[1], bh[3]);
                    mma16816(c[mi][ng * 2 + 0], ah[mi], bl[0], bl[2]);
                    mma16816(c[mi][ng * 2 + 1], ah[mi], bl[1], bl[3]);
                }
            }
        }
        __syncthreads();
        if (it + 2 < G1_NIT) {
            int k0 = (it + 2) * 64;
            ldtile<128, 256>(st + G1_SA, g_wt, m0, k0, FIN, tid);
            ldtile<256, 256>(st + G1_SBH, g_xh, n0, k0, FIN, tid);
            ldtile<256, 256>(st + G1_SBL, g_xl, n0, k0, FIN, tid);
        }
        cp_commit();
    }

    // Epilogue: write single fp16 (XW)^T [f][j]
    int fr = m0 + wm * 64 + (lane >> 2);
    int jc = n0 + wn * 64 + (lane & 3) * 2;
#pragma unroll
    for (int mi = 0; mi < 4; ++mi) {
        int fa = fr + mi * 16, fb = fa + 8;
#pragma unroll
        for (int ni = 0; ni < 8; ++ni) {
            int j = jc + ni * 8;
            *reinterpret_cast<uint32_t*>(g_xwt + (size_t)fa * NROWS + j) =
                pack_h2(c[mi][ni][0], c[mi][ni][1]);
            *reinterpret_cast<uint32_t*>(g_xwt + (size_t)fb * NROWS + j) =
                pack_h2(c[mi][ni][2], c[mi][ni][3]);
        }
    }
}

// =====================================================================================
// GEMM2: D[i][f] = sum_j adj[j][i] * xwt[f][j]; fused in-degree + norm + relu.
// A path: LDG int32 adj -> register convert -> STS fp16 into double-buffered [j][i]
// tile (adj never staged in smem as int32; kills 96KB/iter of crossbar traffic).
// B path: 4-stage cp.async. 512 threads (16 warps 2m x 8n; warp 64i x 32f).
// Tile 128x256x64. Grid 2(n) x 64(m) = 128 CTAs = one wave.
// =====================================================================================
#define G2_SB    0            // fp16 B stages: 4 x 32768
#define G2_SAH   131072       // fp16 converted A: 2 x 16384 (double buffer)
#define G2_SMEM  163840
#define G2_NIT   (NROWS / 64)

__global__ void __launch_bounds__(512, 1) gemm2_kernel(const int* __restrict__ adj,
                                                       float* __restrict__ out) {
    __shared__ int sdeg[128];
    extern __shared__ __align__(1024) char smem[];
    uint32_t sb = smem_u32(smem);
    int tid = threadIdx.x, lane = tid & 31, warp = tid >> 5;
    int wm = warp >> 3, wn = warp & 7;         // 2m x 8n warp grid
    int n0 = blockIdx.x * 256;                 // f
    int m0 = blockIdx.y * 128;                 // i

    if (tid < 128) sdeg[tid] = 0;

    // B (xwt) ldmatrix addresses (non-trans), rows = f, 128B rows
    int lr = lane & 15, lc = lane >> 4;
    int sw = lr & 7;
    uint32_t bRow[2], chk[4];
#pragma unroll
    for (int ng = 0; ng < 2; ++ng) bRow[ng] = (wn * 32 + ng * 16 + lr) * 128;
#pragma unroll
    for (int kc = 0; kc < 4; ++kc) chk[kc] = (uint32_t)((2 * kc + lc) ^ sw) << 4;

    // A trans-ldmatrix addresses: smem tile S[j][i], 256B rows, chunk swizzle ci^(j&7).
    int jb   = ((lane >> 4) & 1) * 8 + (lane & 7);   // row within 16-j window
    int icof = ((lane >> 3) & 1) * 8;                // +8 i for groups 1 and 3
    uint32_t aAddr[4];
#pragma unroll
    for (int mi = 0; mi < 4; ++mi) {
        int ic = wm * 64 + mi * 16 + icof;
        int ci = ic >> 3;
        aAddr[mi] = (uint32_t)(jb * 256 + ((ci ^ (lane & 7)) << 4));
    }

    // A LDG/convert mapping: warp w owns rows j = 4w..4w+3; lane owns i = lane*4..+3
    int cv_i4 = lane * 4;
    uint32_t sts_base = (uint32_t)(((uint32_t)(lane >> 1) << 4) ^ 0u) + (uint32_t)((lane & 1) * 8);
    int d0 = 0, d1 = 0, d2 = 0, d3 = 0;

    float c[4][4][4];
#pragma unroll
    for (int mi = 0; mi < 4; ++mi)
#pragma unroll
        for (int ni = 0; ni < 4; ++ni)
#pragma unroll
            for (int q = 0; q < 4; ++q) c[mi][ni][q] = 0.0f;

    // LDG tile 0
    int4 areg[4];
#pragma unroll
    for (int jj = 0; jj < 4; ++jj)
        areg[jj] = *reinterpret_cast<const int4*>(adj + (size_t)(4 * warp + jj) * NROWS + m0 + cv_i4);

    // prefetch 4 B stages
#pragma unroll
    for (int s = 0; s < 4; ++s) {
        ldtile<256, 512>(sb + G2_SB + s * 32768, g_xwt, n0, s * 64, NROWS, tid);
        cp_commit();
    }

    // convert tile 0 -> AH[0]
    {
        uint32_t dst0 = sb + G2_SAH;
#pragma unroll
        for (int jj = 0; jj < 4; ++jj) {
            int j = 4 * warp + jj;
            int4 v = areg[jj];
            d0 += v.x; d1 += v.y; d2 += v.z; d3 += v.w;
            uint2 pv;
            pv.x = (uint32_t)(v.x | (v.y << 16)) * 0x3C00u;
            pv.y = (uint32_t)(v.z | (v.w << 16)) * 0x3C00u;
            uint32_t addr = dst0 + j * 256 + ((((uint32_t)(lane >> 1)) ^ (uint32_t)(j & 7)) << 4) + (lane & 1) * 8;
            *reinterpret_cast<uint2*>((char*)smem + (addr - sb)) = pv;
        }
    }

    for (int it = 0; it < G2_NIT; ++it) {
        // ---- issue A LDG for tile it+1 early (latency hidden under MMA phase) ----
        if (it + 1 < G2_NIT) {
#pragma unroll
            for (int jj = 0; jj < 4; ++jj)
                areg[jj] = *reinterpret_cast<const int4*>(
                    adj + (size_t)((it + 1) * 64 + 4 * warp + jj) * NROWS + m0 + cv_i4);
        }

        cp_wait<3>();
        __syncthreads();   // B stage it ready; AH[it&1] (written last iter) visible

        // ---- compute from AH[it&1] + B stage it&3 ----
        uint32_t sta = sb + G2_SAH + (uint32_t)(it & 1) * 16384;
        uint32_t stb = sb + G2_SB + (uint32_t)(it & 3) * 32768;
#pragma unroll
        for (int kc = 0; kc < 4; ++kc) {
            uint32_t a[4][4];
#pragma unroll
            for (int mi = 0; mi < 4; ++mi)
                ldsm4t(a[mi], sta + kc * 4096 + aAddr[mi]);
#pragma unroll
            for (int ng = 0; ng < 2; ++ng) {
                uint32_t b[4];
                ldsm4(b, stb + bRow[ng] + chk[kc]);
#pragma unroll
                for (int mi = 0; mi < 4; ++mi) {
                    mma16816(c[mi][ng * 2 + 0], a[mi], b[0], b[2]);
                    mma16816(c[mi][ng * 2 + 1], a[mi], b[1], b[3]);
                }
            }
        }

        // ---- convert regs -> AH[(it+1)&1]  (overlaps other warps' MMAs) ----
        if (it + 1 < G2_NIT) {
            uint32_t dst0 = sb + G2_SAH + (uint32_t)((it + 1) & 1) * 16384;
#pragma unroll
            for (int jj = 0; jj < 4; ++jj) {
                int j = 4 * warp + jj;
                int4 v = areg[jj];
                d0 += v.x; d1 += v.y; d2 += v.z; d3 += v.w;
                uint2 pv;
                pv.x = (uint32_t)(v.x | (v.y << 16)) * 0x3C00u;
                pv.y = (uint32_t)(v.z | (v.w << 16)) * 0x3C00u;
                uint32_t addr = dst0 + j * 256 + ((((uint32_t)(lane >> 1)) ^ (uint32_t)(j & 7)) << 4) + (lane & 1) * 8;
                *reinterpret_cast<uint2*>((char*)smem + (addr - sb)) = pv;
            }
        }
        __syncthreads();   // all reads of B stage it&3 done; AH writes published next iter

        // ---- prefetch B tile it+4 into just-freed stage ----
        if (it + 4 < G2_NIT)
            ldtile<256, 512>(sb + G2_SB + (uint32_t)(it & 3) * 32768, g_xwt, n0, (it + 4) * 64, NROWS, tid);
        cp_commit();
    }

    // ---- degree reduce -> norm ----
    atomicAdd(&sdeg[cv_i4 + 0], d0);
    atomicAdd(&sdeg[cv_i4 + 1], d1);
    atomicAdd(&sdeg[cv_i4 + 2], d2);
    atomicAdd(&sdeg[cv_i4 + 3], d3);
    __syncthreads();

    // ---- epilogue: out[i][f] = relu(c * rsqrt(max(deg,1))) ----
    int il = wm * 64 + (lane >> 2);
    int fc = n0 + wn * 32 + (lane & 3) * 2;
#pragma unroll
    for (int mi = 0; mi < 4; ++mi) {
        int ial = il + mi * 16, ibl = ial + 8;
        float na = rsqrtf(fmaxf((float)sdeg[ial], 1.0f));
        float nb = rsqrtf(fmaxf((float)sdeg[ibl], 1.0f));
        float* oa = out + (size_t)(m0 + ial) * FOUT;
        float* ob = out + (size_t)(m0 + ibl) * FOUT;
#pragma unroll
        for (int ni = 0; ni < 4; ++ni) {
            int f = fc + ni * 8;
            float2 va, vb;
            va.x = fmaxf(c[mi][ni][0] * na, 0.0f);
            va.y = fmaxf(c[mi][ni][1] * na, 0.0f);
            vb.x = fmaxf(c[mi][ni][2] * nb, 0.0f);
            vb.y = fmaxf(c[mi][ni][3] * nb, 0.0f);
            *reinterpret_cast<float2*>(oa + f) = va;
            *reinterpret_cast<float2*>(ob + f) = vb;
        }
    }
}

// ---------------- launch ----------------
extern "C" void kernel_launch(void* const* d_in, const int* in_sizes, int n_in,
                              void* d_out, int out_size) {
    const float* X   = (const float*)d_in[0];
    const int*   adj = (const int*)d_in[1];
    const float* W   = (const float*)d_in[2];
    float*       out = (float*)d_out;

    cudaFuncSetAttribute(gemm1_kernel, cudaFuncAttributeMaxDynamicSharedMemorySize, G1_SMEM);
    cudaFuncSetAttribute(gemm2_kernel, cudaFuncAttributeMaxDynamicSharedMemorySize, G2_SMEM);

    splitx_kernel<<<1024, 256>>>(X);
    prepw_kernel<<<(FIN * FOUT + 255) / 256, 256>>>(W);

    gemm1_kernel<<<dim3(NROWS / 256, FIN / 128), 256, G1_SMEM>>>();
    gemm2_kernel<<<dim3(FOUT / 256, NROWS / 128), 512, G2_SMEM>>>(adj, out);
}